// round 1
// baseline (speedup 1.0000x reference)
#include <cuda_runtime.h>
#include <math.h>
#include <stdint.h>

// ---------------------------------------------------------------------------
// MLA forward, fp32 baseline.
// B=2, T=2048, C=2048, H=16, DH=128, L=512, hd2=64
// rows = B*T = 4096
// ---------------------------------------------------------------------------

#define ROWS 4096
#define TDIM 2048
#define CDIM 2048
#define LDIM 512
#define HNUM 16
#define DH   128
#define HD2  64

// ------------------------- scratch (device globals) ------------------------
__device__ float g_kvd [ROWS * LDIM];          // 8 MB
__device__ float g_qd  [ROWS * LDIM];          // 8 MB
__device__ float g_kc  [ROWS * 1024];          // 16 MB
__device__ float g_qc  [ROWS * 1024];          // 16 MB
__device__ float g_vl  [ROWS * CDIM];          // 32 MB
__device__ float g_kr  [ROWS * 1024];          // 16 MB
__device__ float g_qr  [ROWS * 1024];          // 16 MB
__device__ float g_Q   [2 * HNUM * TDIM * DH]; // 32 MB  [b,h,t,d]
__device__ float g_K   [2 * HNUM * TDIM * DH]; // 32 MB
__device__ float g_V   [2 * HNUM * TDIM * DH]; // 32 MB
__device__ float g_attn[ROWS * CDIM];          // 32 MB

// ------------------------------- GEMM NT -----------------------------------
// C[M,N] = A[M,K] * B[N,K]^T   (all row-major, M%64==0, N%64==0, K%16==0)
__global__ __launch_bounds__(256) void gemm_nt(
    const float* __restrict__ A, const float* __restrict__ B,
    float* __restrict__ C, int M, int N, int K)
{
    __shared__ float As[16][68];   // As[k][m] (transposed tile)
    __shared__ float Bs[16][68];   // Bs[k][n]
    const int tid = threadIdx.x;
    const int tx = tid & 15, ty = tid >> 4;
    const int bm = blockIdx.y * 64, bn = blockIdx.x * 64;

    float acc[4][4];
#pragma unroll
    for (int i = 0; i < 4; i++)
#pragma unroll
        for (int j = 0; j < 4; j++) acc[i][j] = 0.f;

    for (int k0 = 0; k0 < K; k0 += 16) {
#pragma unroll
        for (int r = 0; r < 4; r++) {
            int l = tid + r * 256;          // 0..1023
            int m = l >> 4, kk = l & 15;
            As[kk][m] = A[(size_t)(bm + m) * K + (k0 + kk)];
            Bs[kk][m] = B[(size_t)(bn + m) * K + (k0 + kk)];
        }
        __syncthreads();
#pragma unroll
        for (int kk = 0; kk < 16; kk++) {
            float4 a4 = *(const float4*)&As[kk][ty * 4];
            float4 b4 = *(const float4*)&Bs[kk][tx * 4];
            float a[4] = {a4.x, a4.y, a4.z, a4.w};
            float bb[4] = {b4.x, b4.y, b4.z, b4.w};
#pragma unroll
            for (int i = 0; i < 4; i++)
#pragma unroll
                for (int j = 0; j < 4; j++)
                    acc[i][j] += a[i] * bb[j];
        }
        __syncthreads();
    }
#pragma unroll
    for (int i = 0; i < 4; i++) {
        size_t off = (size_t)(bm + ty * 4 + i) * N + bn + tx * 4;
        float4 v = make_float4(acc[i][0], acc[i][1], acc[i][2], acc[i][3]);
        *(float4*)&C[off] = v;
    }
}

// ------------------------------- RoPE --------------------------------------
// In-place interleaved rope on [ROWS, 1024]; pos = row % TDIM.
// Matches reference: freq & ang computed in fp32, then sin/cos of that fp32
// value (double range-reduction keeps accuracy even under fast-math).
__global__ void rope_kernel(float* __restrict__ x)
{
    int idx = blockIdx.x * blockDim.x + threadIdx.x;   // one per pair
    if (idx >= ROWS * 512) return;
    int pair = idx & 511;
    int row  = idx >> 9;
    int t    = row & (TDIM - 1);

    const float c1 = (float)(-9.210340371976184 / 1024.0);  // -ln(1e4)/D
    float f   = expf((float)(2 * pair) * c1);
    float ang = (float)t * f;                                // fp32, as ref

    // exact-enough range reduction in double, then fp32 sin/cos
    double ad = (double)ang;
    double r  = ad - floor(ad * 0.15915494309189535) * 6.283185307179586;
    float s = sinf((float)r);
    float c = cosf((float)r);

    float* p = x + (size_t)row * 1024 + 2 * pair;
    float xe = p[0], xo = p[1];
    p[0] = xe * c - xo * s;
    p[1] = xo * c + xe * s;
}

// ------------------------------- pack Q/K/V --------------------------------
// Q/K/V layout: [b, h, t, d] with d in [0,128): d<64 from *_c, d>=64 from *_r
__global__ void pack_qkv(const float* __restrict__ qc, const float* __restrict__ qr,
                         const float* __restrict__ kc, const float* __restrict__ kr,
                         const float* __restrict__ vl,
                         float* __restrict__ Q, float* __restrict__ K,
                         float* __restrict__ V)
{
    int idx = blockIdx.x * blockDim.x + threadIdx.x;
    if (idx >= 2 * HNUM * TDIM * DH) return;
    int d = idx & 127;
    int t = (idx >> 7) & (TDIM - 1);
    int h = (idx >> 18) & (HNUM - 1);
    int b = idx >> 22;
    int row = b * TDIM + t;

    float qv, kv;
    if (d < HD2) {
        qv = qc[(size_t)row * 1024 + h * HD2 + d];
        kv = kc[(size_t)row * 1024 + h * HD2 + d];
    } else {
        qv = qr[(size_t)row * 1024 + h * HD2 + (d - HD2)];
        kv = kr[(size_t)row * 1024 + h * HD2 + (d - HD2)];
    }
    Q[idx] = qv;
    K[idx] = kv;
    V[idx] = vl[(size_t)row * CDIM + h * DH + d];
}

// ---------------------------- flash attention ------------------------------
// One block = (qb, h, b): 64 query rows, loop over causal 64-key tiles.
// 256 threads: thread (ty,tx) owns S micro-tile rows ty*4..+3 / cols tx*4..+3
// and O micro-tile rows ty*4..+3 / d-cols tx*8..+7.
#define ATTN_SMEM_FLOATS (128*68*2 + 64*132 + 64*65)

__global__ __launch_bounds__(256) void attn_kernel(
    const float* __restrict__ Q, const float* __restrict__ K,
    const float* __restrict__ V, float* __restrict__ Og)
{
    extern __shared__ float sm[];
    float* Qs = sm;                 // [128][68]  transposed: Qs[d][r]
    float* Ks = Qs + 128 * 68;      // [128][68]  transposed: Ks[d][r]
    float* Vs = Ks + 128 * 68;      // [64][132]  row-major
    float* Ss = Vs + 64 * 132;      // [64][65]   probabilities

    const int qb = blockIdx.x, h = blockIdx.y, b = blockIdx.z;
    const int tid = threadIdx.x;
    const int tx = tid & 15, ty = tid >> 4;
    const size_t base = (size_t)(b * HNUM + h) * TDIM * DH;
    const int q0 = qb * 64;
    const float scale = 0.08838834764831845f;  // 1/sqrt(128)

    // load Q tile transposed
    for (int l = tid; l < 64 * 128; l += 256) {
        int r = l >> 7, c = l & 127;
        Qs[c * 68 + r] = Q[base + (size_t)(q0 + r) * DH + c];
    }

    float m_old[4], l_sum[4], o[4][8];
#pragma unroll
    for (int i = 0; i < 4; i++) {
        m_old[i] = -INFINITY; l_sum[i] = 0.f;
#pragma unroll
        for (int j = 0; j < 8; j++) o[i][j] = 0.f;
    }

    for (int kb = 0; kb <= qb; kb++) {
        __syncthreads();   // protect K/V smem reuse (covers Q on iter 0 via next sync)
        for (int l = tid; l < 64 * 128; l += 256) {
            int r = l >> 7, c = l & 127;
            Ks[c * 68 + r] = K[base + (size_t)(kb * 64 + r) * DH + c];
            Vs[r * 132 + c] = V[base + (size_t)(kb * 64 + r) * DH + c];
        }
        __syncthreads();

        // ---- S = scale * Q K^T (4x4 micro-tile) ----
        float acc[4][4];
#pragma unroll
        for (int i = 0; i < 4; i++)
#pragma unroll
            for (int j = 0; j < 4; j++) acc[i][j] = 0.f;

        for (int d = 0; d < 128; d++) {
            float4 qa = *(const float4*)&Qs[d * 68 + ty * 4];
            float4 ka = *(const float4*)&Ks[d * 68 + tx * 4];
            float a[4] = {qa.x, qa.y, qa.z, qa.w};
            float bb[4] = {ka.x, ka.y, ka.z, ka.w};
#pragma unroll
            for (int i = 0; i < 4; i++)
#pragma unroll
                for (int j = 0; j < 4; j++)
                    acc[i][j] += a[i] * bb[j];
        }

        const bool diag = (kb == qb);
        float alpha[4];
#pragma unroll
        for (int ii = 0; ii < 4; ii++) {
            int qg = ty * 4 + ii;
            float mx = -INFINITY;
#pragma unroll
            for (int jj = 0; jj < 4; jj++) {
                float s = acc[ii][jj] * scale;
                if (diag && (tx * 4 + jj > qg)) s = -INFINITY;
                acc[ii][jj] = s;
                mx = fmaxf(mx, s);
            }
            // reduce across the 16 lanes sharing this row (tx = lane&15)
            mx = fmaxf(mx, __shfl_xor_sync(0xffffffffu, mx, 1));
            mx = fmaxf(mx, __shfl_xor_sync(0xffffffffu, mx, 2));
            mx = fmaxf(mx, __shfl_xor_sync(0xffffffffu, mx, 4));
            mx = fmaxf(mx, __shfl_xor_sync(0xffffffffu, mx, 8));
            float m_new = fmaxf(m_old[ii], mx);
            alpha[ii] = expf(m_old[ii] - m_new);
            float ps = 0.f;
#pragma unroll
            for (int jj = 0; jj < 4; jj++) {
                float pv = expf(acc[ii][jj] - m_new);
                Ss[(size_t)qg * 65 + tx * 4 + jj] = pv;
                ps += pv;
            }
            ps += __shfl_xor_sync(0xffffffffu, ps, 1);
            ps += __shfl_xor_sync(0xffffffffu, ps, 2);
            ps += __shfl_xor_sync(0xffffffffu, ps, 4);
            ps += __shfl_xor_sync(0xffffffffu, ps, 8);
            l_sum[ii] = l_sum[ii] * alpha[ii] + ps;
            m_old[ii] = m_new;
        }

        // rescale O
#pragma unroll
        for (int ii = 0; ii < 4; ii++)
#pragma unroll
            for (int jj = 0; jj < 8; jj++) o[ii][jj] *= alpha[ii];

        __syncwarp();   // Ss rows are produced+consumed within one warp

        // ---- O += P V (4 rows x 8 d-cols) ----
#pragma unroll 4
        for (int j = 0; j < 64; j++) {
            float4 v0 = *(const float4*)&Vs[j * 132 + tx * 8];
            float4 v1 = *(const float4*)&Vs[j * 132 + tx * 8 + 4];
#pragma unroll
            for (int ii = 0; ii < 4; ii++) {
                float pv = Ss[(size_t)(ty * 4 + ii) * 65 + j];
                o[ii][0] += pv * v0.x; o[ii][1] += pv * v0.y;
                o[ii][2] += pv * v0.z; o[ii][3] += pv * v0.w;
                o[ii][4] += pv * v1.x; o[ii][5] += pv * v1.y;
                o[ii][6] += pv * v1.z; o[ii][7] += pv * v1.w;
            }
        }
        __syncwarp();
    }

    // write normalized output to attn buffer: [row, h*128 + d]
#pragma unroll
    for (int ii = 0; ii < 4; ii++) {
        float inv = 1.f / l_sum[ii];
        int qg = q0 + ty * 4 + ii;
        size_t off = (size_t)(b * TDIM + qg) * CDIM + h * DH + tx * 8;
#pragma unroll
        for (int jj = 0; jj < 8; jj++)
            Og[off + jj] = o[ii][jj] * inv;
    }
}

// ------------------------------- launch ------------------------------------
static void launch_gemm(const float* A, const float* B, float* C,
                        int M, int N, int K)
{
    dim3 grid(N / 64, M / 64);
    gemm_nt<<<grid, 256>>>(A, B, C, M, N, K);
}

extern "C" void kernel_launch(void* const* d_in, const int* in_sizes, int n_in,
                              void* d_out, int out_size)
{
    (void)in_sizes; (void)n_in; (void)out_size;
    const float* x    = (const float*)d_in[0];
    const float* WkvD = (const float*)d_in[1];
    const float* WqD  = (const float*)d_in[2];
    const float* WkU  = (const float*)d_in[3];
    const float* WvU  = (const float*)d_in[4];
    const float* WqU  = (const float*)d_in[5];
    const float* Wrk  = (const float*)d_in[6];
    const float* Wrq  = (const float*)d_in[7];
    const float* Wo   = (const float*)d_in[8];
    float* out = (float*)d_out;

    float *kvd, *qd, *kc, *qc, *vl, *kr, *qr, *Qh, *Kh, *Vh, *attn;
    cudaGetSymbolAddress((void**)&kvd,  g_kvd);
    cudaGetSymbolAddress((void**)&qd,   g_qd);
    cudaGetSymbolAddress((void**)&kc,   g_kc);
    cudaGetSymbolAddress((void**)&qc,   g_qc);
    cudaGetSymbolAddress((void**)&vl,   g_vl);
    cudaGetSymbolAddress((void**)&kr,   g_kr);
    cudaGetSymbolAddress((void**)&qr,   g_qr);
    cudaGetSymbolAddress((void**)&Qh,   g_Q);
    cudaGetSymbolAddress((void**)&Kh,   g_K);
    cudaGetSymbolAddress((void**)&Vh,   g_V);
    cudaGetSymbolAddress((void**)&attn, g_attn);

    // projections
    launch_gemm(x,   WkvD, kvd, ROWS,  LDIM, CDIM);   // kv_d
    launch_gemm(x,   WqD,  qd,  ROWS,  LDIM, CDIM);   // q_d
    launch_gemm(kvd, WkU,  kc,  ROWS,  1024, LDIM);   // k_c
    launch_gemm(qd,  WqU,  qc,  ROWS,  1024, LDIM);   // q_c
    launch_gemm(kvd, WvU,  vl,  ROWS,  CDIM, LDIM);   // v
    launch_gemm(x,   Wrk,  kr,  ROWS,  1024, CDIM);   // k_r (pre-rope)
    launch_gemm(qd,  Wrq,  qr,  ROWS,  1024, LDIM);   // q_r (pre-rope)

    // rope (in-place), one thread per pair
    {
        int n = ROWS * 512;
        rope_kernel<<<(n + 255) / 256, 256>>>(kr);
        rope_kernel<<<(n + 255) / 256, 256>>>(qr);
    }

    // pack into [b,h,t,d]
    {
        int n = 2 * HNUM * TDIM * DH;
        pack_qkv<<<(n + 255) / 256, 256>>>(qc, qr, kc, kr, vl, Qh, Kh, Vh);
    }

    // flash attention
    {
        size_t smem = ATTN_SMEM_FLOATS * sizeof(float);
        cudaFuncSetAttribute(attn_kernel,
                             cudaFuncAttributeMaxDynamicSharedMemorySize,
                             (int)smem);
        dim3 grid(TDIM / 64, HNUM, 2);
        attn_kernel<<<grid, 256, smem>>>(Qh, Kh, Vh, attn);
    }

    // output projection
    launch_gemm(attn, Wo, out, ROWS, CDIM, CDIM);
}

// round 3
// speedup vs baseline: 1.3543x; 1.3543x over previous
#include <cuda_runtime.h>
#include <math.h>
#include <stdint.h>

// ---------------------------------------------------------------------------
// MLA forward. GEMMs via mma.sync tf32 (3xTF32 compensation), attention fp32.
// B=2, T=2048, C=2048, H=16, DH=128, L=512, hd2=64, rows = B*T = 4096
// NOTE: harness ptxas target is compute_100 (no 'a') -> tcgen05 unavailable;
//       mma.sync (HMMA) is the tensor-core path that compiles there.
// ---------------------------------------------------------------------------

#define ROWS 4096
#define TDIM 2048
#define CDIM 2048
#define LDIM 512
#define HNUM 16
#define DH   128
#define HD2  64

// ------------------------- scratch (device globals) ------------------------
__device__ float g_kvd [ROWS * LDIM];
__device__ float g_qd  [ROWS * LDIM];
__device__ float g_kc  [ROWS * 1024];
__device__ float g_qc  [ROWS * 1024];
__device__ float g_vl  [ROWS * CDIM];
__device__ float g_kr  [ROWS * 1024];
__device__ float g_qr  [ROWS * 1024];
__device__ float g_Q   [2 * HNUM * TDIM * DH];
__device__ float g_K   [2 * HNUM * TDIM * DH];
__device__ float g_V   [2 * HNUM * TDIM * DH];
__device__ float g_attn[ROWS * CDIM];

// =========================== helpers =======================================
__device__ __forceinline__ uint32_t smem_u32(const void* p) {
    uint32_t a;
    asm("{ .reg .u64 t; cvta.to.shared.u64 t, %1; cvt.u32.u64 %0, t; }"
        : "=r"(a) : "l"(p));
    return a;
}

__device__ __forceinline__ void cp16(uint32_t dst, const void* src) {
    asm volatile("cp.async.cg.shared.global [%0], [%1], 16;"
                 :: "r"(dst), "l"(src));
}
#define CP_COMMIT() asm volatile("cp.async.commit_group;" ::: "memory")
#define CP_WAIT(n)  asm volatile("cp.async.wait_group %0;" :: "n"(n) : "memory")

__device__ __forceinline__ uint32_t tf32_hi(float x) {
    uint32_t u;
    asm("cvt.rna.tf32.f32 %0, %1;" : "=r"(u) : "f"(x));
    return u;
}

// D += A * B  (m16n8k8 tf32, row.col)
__device__ __forceinline__ void mma_tf32(float* d, const uint32_t* a,
                                         const uint32_t* b) {
    asm volatile(
        "mma.sync.aligned.m16n8k8.row.col.f32.tf32.tf32.f32 "
        "{%0,%1,%2,%3}, {%4,%5,%6,%7}, {%8,%9}, {%0,%1,%2,%3};"
        : "+f"(d[0]), "+f"(d[1]), "+f"(d[2]), "+f"(d[3])
        : "r"(a[0]), "r"(a[1]), "r"(a[2]), "r"(a[3]), "r"(b[0]), "r"(b[1]));
}

// ====================== mma.sync 3xTF32 GEMM ===============================
// C[M,N] = A[M,K] * B[N,K]^T, row-major, M%128==0, N%128==0, K%32==0.
// CTA: 128x128 tile, 256 threads (8 warps, 2x4), warp tile 64x32.
// smem: 3 stages x (A 128x36 + B 128x36) fp32, padded for conflict-free LDS.
#define GPAD     36
#define GST_B    (128 * GPAD * 4)            // 18432 B per operand tile
#define GSTAGE_B (2 * GST_B)                 // 36864 B per stage
#define GEMM_SMEM (3 * GSTAGE_B)             // 110592 B

__global__ __launch_bounds__(256) void gemm_mma(
    const float* __restrict__ A, const float* __restrict__ B,
    float* __restrict__ C, int M, int N, int K)
{
    extern __shared__ __align__(16) float sm[];
    const uint32_t smb = smem_u32(sm);
    const int tid  = threadIdx.x;
    const int wid  = tid >> 5, lane = tid & 31;
    const int wm   = wid >> 2, wn = wid & 3;      // warp grid 2(m) x 4(n)
    const int r    = lane >> 2, q = lane & 3;
    const int bm   = blockIdx.y * 128, bn = blockIdx.x * 128;

    float c[4][4][4];
#pragma unroll
    for (int i = 0; i < 4; i++)
#pragma unroll
        for (int j = 0; j < 4; j++)
#pragma unroll
            for (int e = 0; e < 4; e++) c[i][j][e] = 0.f;

    const int KT = K / 32;

    // ---- async loaders ----
    auto issue = [&](int s, int k0) {
#pragma unroll
        for (int j = 0; j < 4; j++) {
            int f = tid + j * 256;
            int row = f >> 3, c4 = f & 7;
            uint32_t off = (uint32_t)(s * GSTAGE_B + row * (GPAD * 4) + c4 * 16);
            cp16(smb + off, &A[(size_t)(bm + row) * K + k0 + c4 * 4]);
            cp16(smb + off + GST_B, &B[(size_t)(bn + row) * K + k0 + c4 * 4]);
        }
    };

    // prologue: stages 0,1
    issue(0, 0);  CP_COMMIT();
    issue(1, 32); CP_COMMIT();

    for (int it = 0; it < KT; it++) {
        CP_WAIT(1);
        __syncthreads();

        if (it + 2 < KT) issue((it + 2) % 3, (it + 2) * 32);
        CP_COMMIT();

        const float* As = sm + (it % 3) * (GSTAGE_B / 4);
        const float* Bs = As + (GST_B / 4);

#pragma unroll
        for (int ks = 0; ks < 4; ks++) {
            uint32_t Ahi[4][4], Alo[4][4], Bhi[4][2], Blo[4][2];
#pragma unroll
            for (int i = 0; i < 4; i++) {
                int rb = wm * 64 + i * 16 + r;
                int cc = ks * 8 + q;
                float x0 = As[rb * GPAD + cc];
                float x1 = As[(rb + 8) * GPAD + cc];
                float x2 = As[rb * GPAD + cc + 4];
                float x3 = As[(rb + 8) * GPAD + cc + 4];
                Ahi[i][0] = tf32_hi(x0); Alo[i][0] = __float_as_uint(x0 - __uint_as_float(Ahi[i][0]));
                Ahi[i][1] = tf32_hi(x1); Alo[i][1] = __float_as_uint(x1 - __uint_as_float(Ahi[i][1]));
                Ahi[i][2] = tf32_hi(x2); Alo[i][2] = __float_as_uint(x2 - __uint_as_float(Ahi[i][2]));
                Ahi[i][3] = tf32_hi(x3); Alo[i][3] = __float_as_uint(x3 - __uint_as_float(Ahi[i][3]));
            }
#pragma unroll
            for (int j = 0; j < 4; j++) {
                int nb = wn * 32 + j * 8 + r;
                int cc = ks * 8 + q;
                float y0 = Bs[nb * GPAD + cc];
                float y1 = Bs[nb * GPAD + cc + 4];
                Bhi[j][0] = tf32_hi(y0); Blo[j][0] = __float_as_uint(y0 - __uint_as_float(Bhi[j][0]));
                Bhi[j][1] = tf32_hi(y1); Blo[j][1] = __float_as_uint(y1 - __uint_as_float(Bhi[j][1]));
            }
#pragma unroll
            for (int i = 0; i < 4; i++)
#pragma unroll
                for (int j = 0; j < 4; j++) {
                    mma_tf32(c[i][j], Ahi[i], Bhi[j]);
                    mma_tf32(c[i][j], Alo[i], Bhi[j]);
                    mma_tf32(c[i][j], Ahi[i], Blo[j]);
                }
        }
    }

    // ---- epilogue: fragment-layout float2 stores ----
#pragma unroll
    for (int i = 0; i < 4; i++)
#pragma unroll
        for (int j = 0; j < 4; j++) {
            int row0 = bm + wm * 64 + i * 16 + r;
            int col  = bn + wn * 32 + j * 8 + 2 * q;
            *(float2*)&C[(size_t)row0 * N + col]       = make_float2(c[i][j][0], c[i][j][1]);
            *(float2*)&C[(size_t)(row0 + 8) * N + col] = make_float2(c[i][j][2], c[i][j][3]);
        }
}

// ------------------------------- RoPE --------------------------------------
__global__ void rope_kernel(float* __restrict__ x)
{
    int idx = blockIdx.x * blockDim.x + threadIdx.x;
    if (idx >= ROWS * 512) return;
    int pair = idx & 511;
    int row  = idx >> 9;
    int t    = row & (TDIM - 1);

    const float c1 = (float)(-9.210340371976184 / 1024.0);
    float f   = expf((float)(2 * pair) * c1);
    float ang = (float)t * f;

    double ad = (double)ang;
    double rr = ad - floor(ad * 0.15915494309189535) * 6.283185307179586;
    float s = sinf((float)rr);
    float c = cosf((float)rr);

    float* p = x + (size_t)row * 1024 + 2 * pair;
    float xe = p[0], xo = p[1];
    p[0] = xe * c - xo * s;
    p[1] = xo * c + xe * s;
}

// ------------------------------- pack Q/K/V --------------------------------
__global__ void pack_qkv(const float* __restrict__ qc, const float* __restrict__ qr,
                         const float* __restrict__ kc, const float* __restrict__ kr,
                         const float* __restrict__ vl,
                         float* __restrict__ Q, float* __restrict__ K,
                         float* __restrict__ V)
{
    int idx = blockIdx.x * blockDim.x + threadIdx.x;
    if (idx >= 2 * HNUM * TDIM * DH) return;
    int d = idx & 127;
    int t = (idx >> 7) & (TDIM - 1);
    int h = (idx >> 18) & (HNUM - 1);
    int b = idx >> 22;
    int row = b * TDIM + t;

    float qv, kv;
    if (d < HD2) {
        qv = qc[(size_t)row * 1024 + h * HD2 + d];
        kv = kc[(size_t)row * 1024 + h * HD2 + d];
    } else {
        qv = qr[(size_t)row * 1024 + h * HD2 + (d - HD2)];
        kv = kr[(size_t)row * 1024 + h * HD2 + (d - HD2)];
    }
    Q[idx] = qv;
    K[idx] = kv;
    V[idx] = vl[(size_t)row * CDIM + h * DH + d];
}

// ---------------------------- flash attention ------------------------------
#define ATTN_SMEM_FLOATS (128*68*2 + 64*132 + 64*65)

__global__ __launch_bounds__(256) void attn_kernel(
    const float* __restrict__ Q, const float* __restrict__ K,
    const float* __restrict__ V, float* __restrict__ Og)
{
    extern __shared__ float smf[];
    float* Qs = smf;
    float* Ks = Qs + 128 * 68;
    float* Vs = Ks + 128 * 68;
    float* Ss = Vs + 64 * 132;

    const int qb = blockIdx.x, h = blockIdx.y, b = blockIdx.z;
    const int tid = threadIdx.x;
    const int tx = tid & 15, ty = tid >> 4;
    const size_t base = (size_t)(b * HNUM + h) * TDIM * DH;
    const int q0 = qb * 64;
    const float scale = 0.08838834764831845f;

    for (int l = tid; l < 64 * 128; l += 256) {
        int r = l >> 7, c = l & 127;
        Qs[c * 68 + r] = Q[base + (size_t)(q0 + r) * DH + c];
    }

    float m_old[4], l_sum[4], o[4][8];
#pragma unroll
    for (int i = 0; i < 4; i++) {
        m_old[i] = -INFINITY; l_sum[i] = 0.f;
#pragma unroll
        for (int j = 0; j < 8; j++) o[i][j] = 0.f;
    }

    for (int kb = 0; kb <= qb; kb++) {
        __syncthreads();
        for (int l = tid; l < 64 * 128; l += 256) {
            int r = l >> 7, c = l & 127;
            Ks[c * 68 + r] = K[base + (size_t)(kb * 64 + r) * DH + c];
            Vs[r * 132 + c] = V[base + (size_t)(kb * 64 + r) * DH + c];
        }
        __syncthreads();

        float acc[4][4];
#pragma unroll
        for (int i = 0; i < 4; i++)
#pragma unroll
            for (int j = 0; j < 4; j++) acc[i][j] = 0.f;

        for (int d = 0; d < 128; d++) {
            float4 qa = *(const float4*)&Qs[d * 68 + ty * 4];
            float4 ka = *(const float4*)&Ks[d * 68 + tx * 4];
            float a[4] = {qa.x, qa.y, qa.z, qa.w};
            float bb[4] = {ka.x, ka.y, ka.z, ka.w};
#pragma unroll
            for (int i = 0; i < 4; i++)
#pragma unroll
                for (int j = 0; j < 4; j++)
                    acc[i][j] += a[i] * bb[j];
        }

        const bool diag = (kb == qb);
        float alpha[4];
#pragma unroll
        for (int ii = 0; ii < 4; ii++) {
            int qg = ty * 4 + ii;
            float mx = -INFINITY;
#pragma unroll
            for (int jj = 0; jj < 4; jj++) {
                float s = acc[ii][jj] * scale;
                if (diag && (tx * 4 + jj > qg)) s = -INFINITY;
                acc[ii][jj] = s;
                mx = fmaxf(mx, s);
            }
            mx = fmaxf(mx, __shfl_xor_sync(0xffffffffu, mx, 1));
            mx = fmaxf(mx, __shfl_xor_sync(0xffffffffu, mx, 2));
            mx = fmaxf(mx, __shfl_xor_sync(0xffffffffu, mx, 4));
            mx = fmaxf(mx, __shfl_xor_sync(0xffffffffu, mx, 8));
            float m_new = fmaxf(m_old[ii], mx);
            alpha[ii] = expf(m_old[ii] - m_new);
            float ps = 0.f;
#pragma unroll
            for (int jj = 0; jj < 4; jj++) {
                float pv = expf(acc[ii][jj] - m_new);
                Ss[(size_t)qg * 65 + tx * 4 + jj] = pv;
                ps += pv;
            }
            ps += __shfl_xor_sync(0xffffffffu, ps, 1);
            ps += __shfl_xor_sync(0xffffffffu, ps, 2);
            ps += __shfl_xor_sync(0xffffffffu, ps, 4);
            ps += __shfl_xor_sync(0xffffffffu, ps, 8);
            l_sum[ii] = l_sum[ii] * alpha[ii] + ps;
            m_old[ii] = m_new;
        }

#pragma unroll
        for (int ii = 0; ii < 4; ii++)
#pragma unroll
            for (int jj = 0; jj < 8; jj++) o[ii][jj] *= alpha[ii];

        __syncwarp();

#pragma unroll 4
        for (int j = 0; j < 64; j++) {
            float4 v0 = *(const float4*)&Vs[j * 132 + tx * 8];
            float4 v1 = *(const float4*)&Vs[j * 132 + tx * 8 + 4];
#pragma unroll
            for (int ii = 0; ii < 4; ii++) {
                float pv = Ss[(size_t)(ty * 4 + ii) * 65 + j];
                o[ii][0] += pv * v0.x; o[ii][1] += pv * v0.y;
                o[ii][2] += pv * v0.z; o[ii][3] += pv * v0.w;
                o[ii][4] += pv * v1.x; o[ii][5] += pv * v1.y;
                o[ii][6] += pv * v1.z; o[ii][7] += pv * v1.w;
            }
        }
        __syncwarp();
    }

#pragma unroll
    for (int ii = 0; ii < 4; ii++) {
        float inv = 1.f / l_sum[ii];
        int qg = q0 + ty * 4 + ii;
        size_t off = (size_t)(b * TDIM + qg) * CDIM + h * DH + tx * 8;
#pragma unroll
        for (int jj = 0; jj < 8; jj++)
            Og[off + jj] = o[ii][jj] * inv;
    }
}

// ------------------------------- launch ------------------------------------
static void launch_gemm(const float* A, const float* B, float* C,
                        int M, int N, int K)
{
    dim3 grid(N / 128, M / 128);
    gemm_mma<<<grid, 256, GEMM_SMEM>>>(A, B, C, M, N, K);
}

extern "C" void kernel_launch(void* const* d_in, const int* in_sizes, int n_in,
                              void* d_out, int out_size)
{
    (void)in_sizes; (void)n_in; (void)out_size;
    const float* x    = (const float*)d_in[0];
    const float* WkvD = (const float*)d_in[1];
    const float* WqD  = (const float*)d_in[2];
    const float* WkU  = (const float*)d_in[3];
    const float* WvU  = (const float*)d_in[4];
    const float* WqU  = (const float*)d_in[5];
    const float* Wrk  = (const float*)d_in[6];
    const float* Wrq  = (const float*)d_in[7];
    const float* Wo   = (const float*)d_in[8];
    float* out = (float*)d_out;

    float *kvd, *qd, *kc, *qc, *vl, *kr, *qr, *Qh, *Kh, *Vh, *attn;
    cudaGetSymbolAddress((void**)&kvd,  g_kvd);
    cudaGetSymbolAddress((void**)&qd,   g_qd);
    cudaGetSymbolAddress((void**)&kc,   g_kc);
    cudaGetSymbolAddress((void**)&qc,   g_qc);
    cudaGetSymbolAddress((void**)&vl,   g_vl);
    cudaGetSymbolAddress((void**)&kr,   g_kr);
    cudaGetSymbolAddress((void**)&qr,   g_qr);
    cudaGetSymbolAddress((void**)&Qh,   g_Q);
    cudaGetSymbolAddress((void**)&Kh,   g_K);
    cudaGetSymbolAddress((void**)&Vh,   g_V);
    cudaGetSymbolAddress((void**)&attn, g_attn);

    cudaFuncSetAttribute(gemm_mma, cudaFuncAttributeMaxDynamicSharedMemorySize,
                         GEMM_SMEM);

    // projections (tensor cores, 3xTF32)
    launch_gemm(x,   WkvD, kvd, ROWS,  LDIM, CDIM);
    launch_gemm(x,   WqD,  qd,  ROWS,  LDIM, CDIM);
    launch_gemm(kvd, WkU,  kc,  ROWS,  1024, LDIM);
    launch_gemm(qd,  WqU,  qc,  ROWS,  1024, LDIM);
    launch_gemm(kvd, WvU,  vl,  ROWS,  CDIM, LDIM);
    launch_gemm(x,   Wrk,  kr,  ROWS,  1024, CDIM);
    launch_gemm(qd,  Wrq,  qr,  ROWS,  1024, LDIM);

    // rope
    {
        int n = ROWS * 512;
        rope_kernel<<<(n + 255) / 256, 256>>>(kr);
        rope_kernel<<<(n + 255) / 256, 256>>>(qr);
    }

    // pack into [b,h,t,d]
    {
        int n = 2 * HNUM * TDIM * DH;
        pack_qkv<<<(n + 255) / 256, 256>>>(qc, qr, kc, kr, vl, Qh, Kh, Vh);
    }

    // flash attention (fp32)
    {
        size_t smem = ATTN_SMEM_FLOATS * sizeof(float);
        cudaFuncSetAttribute(attn_kernel,
                             cudaFuncAttributeMaxDynamicSharedMemorySize,
                             (int)smem);
        dim3 grid(TDIM / 64, HNUM, 2);
        attn_kernel<<<grid, 256, smem>>>(Qh, Kh, Vh, attn);
    }

    // output projection (tensor cores)
    launch_gemm(attn, Wo, out, ROWS, CDIM, CDIM);
}

// round 4
// speedup vs baseline: 1.8442x; 1.3617x over previous
#include <cuda_runtime.h>
#include <math.h>
#include <stdint.h>

// ---------------------------------------------------------------------------
// MLA forward. GEMMs + attention on mma.sync tf32 (3xTF32 compensation).
// B=2, T=2048, C=2048, H=16, DH=128, L=512, hd2=64, rows = B*T = 4096
// ---------------------------------------------------------------------------

#define ROWS 4096
#define TDIM 2048
#define CDIM 2048
#define LDIM 512
#define HNUM 16
#define DH   128
#define HD2  64

// ------------------------- scratch (device globals) ------------------------
__device__ float g_kvd [ROWS * LDIM];
__device__ float g_qd  [ROWS * LDIM];
__device__ float g_kc  [ROWS * 1024];
__device__ float g_qc  [ROWS * 1024];
__device__ float g_vl  [ROWS * CDIM];
__device__ float g_kr  [ROWS * 1024];
__device__ float g_qr  [ROWS * 1024];
__device__ float g_attn[ROWS * CDIM];

// =========================== helpers =======================================
__device__ __forceinline__ uint32_t smem_u32(const void* p) {
    uint32_t a;
    asm("{ .reg .u64 t; cvta.to.shared.u64 t, %1; cvt.u32.u64 %0, t; }"
        : "=r"(a) : "l"(p));
    return a;
}

__device__ __forceinline__ void cp16(uint32_t dst, const void* src) {
    asm volatile("cp.async.cg.shared.global [%0], [%1], 16;"
                 :: "r"(dst), "l"(src));
}
#define CP_COMMIT() asm volatile("cp.async.commit_group;" ::: "memory")
#define CP_WAIT(n)  asm volatile("cp.async.wait_group %0;" :: "n"(n) : "memory")

__device__ __forceinline__ uint32_t tf32_hi(float x) {
    uint32_t u;
    asm("cvt.rna.tf32.f32 %0, %1;" : "=r"(u) : "f"(x));
    return u;
}
__device__ __forceinline__ void split32(float x, uint32_t& hi, uint32_t& lo) {
    hi = tf32_hi(x);
    lo = __float_as_uint(x - __uint_as_float(hi));
}

// D += A * B  (m16n8k8 tf32, row.col)
__device__ __forceinline__ void mma_tf32(float* d, const uint32_t* a,
                                         const uint32_t* b) {
    asm volatile(
        "mma.sync.aligned.m16n8k8.row.col.f32.tf32.tf32.f32 "
        "{%0,%1,%2,%3}, {%4,%5,%6,%7}, {%8,%9}, {%0,%1,%2,%3};"
        : "+f"(d[0]), "+f"(d[1]), "+f"(d[2]), "+f"(d[3])
        : "r"(a[0]), "r"(a[1]), "r"(a[2]), "r"(a[3]), "r"(b[0]), "r"(b[1]));
}

// fast exp on the FMA pipe (x <= 0), rel err ~1.2e-7
__device__ __forceinline__ float fexp(float x) {
    float t  = x * 1.4426950408889634f;
    float kf = rintf(t);
    float y  = (t - kf) * 0.6931471805599453f;   // |y| <= 0.3466
    float r  = fmaf(y, 1.3888888889e-3f, 8.3333333333e-3f);
    r = fmaf(y, r, 4.1666666667e-2f);
    r = fmaf(y, r, 1.6666666667e-1f);
    r = fmaf(y, r, 0.5f);
    r = fmaf(y, r, 1.0f);
    r = fmaf(y, r, 1.0f);
    int ki = (int)fmaxf(kf, -127.0f);
    return r * __int_as_float((ki + 127) << 23);
}

// ====================== mma.sync 3xTF32 GEMM (unchanged) ===================
#define GPAD     36
#define GST_B    (128 * GPAD * 4)
#define GSTAGE_B (2 * GST_B)
#define GEMM_SMEM (3 * GSTAGE_B)

__global__ __launch_bounds__(256) void gemm_mma(
    const float* __restrict__ A, const float* __restrict__ B,
    float* __restrict__ C, int M, int N, int K)
{
    extern __shared__ __align__(16) float sm[];
    const uint32_t smb = smem_u32(sm);
    const int tid  = threadIdx.x;
    const int wid  = tid >> 5, lane = tid & 31;
    const int wm   = wid >> 2, wn = wid & 3;
    const int r    = lane >> 2, q = lane & 3;
    const int bm   = blockIdx.y * 128, bn = blockIdx.x * 128;

    float c[4][4][4];
#pragma unroll
    for (int i = 0; i < 4; i++)
#pragma unroll
        for (int j = 0; j < 4; j++)
#pragma unroll
            for (int e = 0; e < 4; e++) c[i][j][e] = 0.f;

    const int KT = K / 32;

    auto issue = [&](int s, int k0) {
#pragma unroll
        for (int j = 0; j < 4; j++) {
            int f = tid + j * 256;
            int row = f >> 3, c4 = f & 7;
            uint32_t off = (uint32_t)(s * GSTAGE_B + row * (GPAD * 4) + c4 * 16);
            cp16(smb + off, &A[(size_t)(bm + row) * K + k0 + c4 * 4]);
            cp16(smb + off + GST_B, &B[(size_t)(bn + row) * K + k0 + c4 * 4]);
        }
    };

    issue(0, 0);  CP_COMMIT();
    issue(1, 32); CP_COMMIT();

    for (int it = 0; it < KT; it++) {
        CP_WAIT(1);
        __syncthreads();

        if (it + 2 < KT) issue((it + 2) % 3, (it + 2) * 32);
        CP_COMMIT();

        const float* As = sm + (it % 3) * (GSTAGE_B / 4);
        const float* Bs = As + (GST_B / 4);

#pragma unroll
        for (int ks = 0; ks < 4; ks++) {
            uint32_t Ahi[4][4], Alo[4][4], Bhi[4][2], Blo[4][2];
#pragma unroll
            for (int i = 0; i < 4; i++) {
                int rb = wm * 64 + i * 16 + r;
                int cc = ks * 8 + q;
                split32(As[rb * GPAD + cc],       Ahi[i][0], Alo[i][0]);
                split32(As[(rb + 8) * GPAD + cc], Ahi[i][1], Alo[i][1]);
                split32(As[rb * GPAD + cc + 4],   Ahi[i][2], Alo[i][2]);
                split32(As[(rb + 8) * GPAD + cc + 4], Ahi[i][3], Alo[i][3]);
            }
#pragma unroll
            for (int j = 0; j < 4; j++) {
                int nb = wn * 32 + j * 8 + r;
                int cc = ks * 8 + q;
                split32(Bs[nb * GPAD + cc],     Bhi[j][0], Blo[j][0]);
                split32(Bs[nb * GPAD + cc + 4], Bhi[j][1], Blo[j][1]);
            }
#pragma unroll
            for (int i = 0; i < 4; i++)
#pragma unroll
                for (int j = 0; j < 4; j++) {
                    mma_tf32(c[i][j], Ahi[i], Bhi[j]);
                    mma_tf32(c[i][j], Alo[i], Bhi[j]);
                    mma_tf32(c[i][j], Ahi[i], Blo[j]);
                }
        }
    }

#pragma unroll
    for (int i = 0; i < 4; i++)
#pragma unroll
        for (int j = 0; j < 4; j++) {
            int row0 = bm + wm * 64 + i * 16 + r;
            int col  = bn + wn * 32 + j * 8 + 2 * q;
            *(float2*)&C[(size_t)row0 * N + col]       = make_float2(c[i][j][0], c[i][j][1]);
            *(float2*)&C[(size_t)(row0 + 8) * N + col] = make_float2(c[i][j][2], c[i][j][3]);
        }
}

// ------------------------------- RoPE (fused kr+qr) ------------------------
__global__ void rope2_kernel(float* __restrict__ xk, float* __restrict__ xq)
{
    int idx = blockIdx.x * blockDim.x + threadIdx.x;
    if (idx >= ROWS * 512) return;
    int pair = idx & 511;
    int row  = idx >> 9;
    int t    = row & (TDIM - 1);

    const float c1 = (float)(-9.210340371976184 / 1024.0);
    float f   = expf((float)(2 * pair) * c1);
    float ang = (float)t * f;

    double ad = (double)ang;
    double rr = ad - floor(ad * 0.15915494309189535) * 6.283185307179586;
    float s = sinf((float)rr);
    float c = cosf((float)rr);

    {
        float* p = xk + (size_t)row * 1024 + 2 * pair;
        float xe = p[0], xo = p[1];
        p[0] = xe * c - xo * s;
        p[1] = xo * c + xe * s;
    }
    {
        float* p = xq + (size_t)row * 1024 + 2 * pair;
        float xe = p[0], xo = p[1];
        p[0] = xe * c - xo * s;
        p[1] = xo * c + xe * s;
    }
}

// ====================== mma.sync flash attention ===========================
// CTA: 128 q-rows x (h, b). 8 warps, each warp owns 16 q-rows (row-local
// softmax). K-tiles 64 keys; K double-buffered, V single-buffered cp.async.
// Reads qc/qr/kc/kr/vl directly (no pack). 3xTF32 everywhere.
#define AT_QF (128 * 132)
#define AT_KF (64 * 132)
#define AT_VF (64 * 132)
#define AT_PF (128 * 68)
#define OFF_Q 0
#define OFF_K (AT_QF)
#define OFF_V (AT_QF + 2 * AT_KF)
#define OFF_P (AT_QF + 2 * AT_KF + AT_VF)
#define ATTN_SMEM ((AT_QF + 2 * AT_KF + AT_VF + AT_PF) * 4)   // 203776 B

__global__ __launch_bounds__(256) void attn_mma(
    const float* __restrict__ qc, const float* __restrict__ qr,
    const float* __restrict__ kc, const float* __restrict__ kr,
    const float* __restrict__ vl, float* __restrict__ Og)
{
    extern __shared__ __align__(16) float sm[];
    const uint32_t smb = smem_u32(sm);
    const int tid = threadIdx.x, wid = tid >> 5, lane = tid & 31;
    const int g = lane >> 2, q = lane & 3;
    const int qb = blockIdx.x, h = blockIdx.y, b = blockIdx.z;
    const int q0 = qb * 128;
    const int rowbase = b * TDIM;
    const float scale = 0.08838834764831845f;   // 1/sqrt(128)

    // ---- prologue: Q + K0 (group 0), V0 (group 1) ----
#pragma unroll
    for (int j = 0; j < 16; j++) {
        int f = tid + j * 256;
        int row = f >> 5, c4 = f & 31;
        const float* src = (c4 < 16)
            ? &qc[(size_t)(rowbase + q0 + row) * 1024 + h * HD2 + c4 * 4]
            : &qr[(size_t)(rowbase + q0 + row) * 1024 + h * HD2 + (c4 - 16) * 4];
        cp16(smb + (OFF_Q + row * 132 + c4 * 4) * 4, src);
    }
#pragma unroll
    for (int j = 0; j < 8; j++) {
        int f = tid + j * 256;
        int row = f >> 5, c4 = f & 31;
        const float* src = (c4 < 16)
            ? &kc[(size_t)(rowbase + row) * 1024 + h * HD2 + c4 * 4]
            : &kr[(size_t)(rowbase + row) * 1024 + h * HD2 + (c4 - 16) * 4];
        cp16(smb + (OFF_K + row * 132 + c4 * 4) * 4, src);
    }
    CP_COMMIT();
#pragma unroll
    for (int j = 0; j < 8; j++) {
        int f = tid + j * 256;
        int row = f >> 5, c4 = f & 31;
        cp16(smb + (OFF_V + row * 132 + c4 * 4) * 4,
             &vl[(size_t)(rowbase + row) * 2048 + h * DH + c4 * 4]);
    }
    CP_COMMIT();

    float o[16][4];
#pragma unroll
    for (int jt = 0; jt < 16; jt++)
#pragma unroll
        for (int e = 0; e < 4; e++) o[jt][e] = 0.f;
    float m_old0 = -1e30f, m_old1 = -1e30f, l0 = 0.f, l1 = 0.f;

    const int kmax = 2 * qb + 1;
    const int gr0 = q0 + 16 * wid + g, gr1 = gr0 + 8;

    for (int kb = 0; kb <= kmax; kb++) {
        // a) issue K_{kb+1}
        if (kb < kmax) {
            int slot = (kb + 1) & 1;
            int tk = (kb + 1) * 64;
#pragma unroll
            for (int j = 0; j < 8; j++) {
                int f = tid + j * 256;
                int row = f >> 5, c4 = f & 31;
                const float* src = (c4 < 16)
                    ? &kc[(size_t)(rowbase + tk + row) * 1024 + h * HD2 + c4 * 4]
                    : &kr[(size_t)(rowbase + tk + row) * 1024 + h * HD2 + (c4 - 16) * 4];
                cp16(smb + (OFF_K + slot * AT_KF + row * 132 + c4 * 4) * 4, src);
            }
        }
        CP_COMMIT();
        CP_WAIT(2);
        __syncthreads();   // K_kb ready; V buffer free

        const bool active = (kb * 64 <= q0 + 16 * wid + 15);
        if (active) {
            const float* Ksb = sm + OFF_K + (kb & 1) * AT_KF;
            const float* Qw  = sm + OFF_Q + (16 * wid) * 132;

            float sacc[8][4];
#pragma unroll
            for (int j = 0; j < 8; j++)
#pragma unroll
                for (int e = 0; e < 4; e++) sacc[j][e] = 0.f;

#pragma unroll 2
            for (int ks = 0; ks < 16; ks++) {
                uint32_t Ah[4], Al[4];
                int cc = ks * 8 + q;
                split32(Qw[g * 132 + cc],           Ah[0], Al[0]);
                split32(Qw[(g + 8) * 132 + cc],     Ah[1], Al[1]);
                split32(Qw[g * 132 + cc + 4],       Ah[2], Al[2]);
                split32(Qw[(g + 8) * 132 + cc + 4], Ah[3], Al[3]);
#pragma unroll
                for (int j = 0; j < 8; j++) {
                    uint32_t Bh[2], Bl[2];
                    split32(Ksb[(j * 8 + g) * 132 + cc],     Bh[0], Bl[0]);
                    split32(Ksb[(j * 8 + g) * 132 + cc + 4], Bh[1], Bl[1]);
                    mma_tf32(sacc[j], Ah, Bh);
                    mma_tf32(sacc[j], Al, Bh);
                    mma_tf32(sacc[j], Ah, Bl);
                }
            }

            // ---- scale + causal mask + online softmax (warp-local) ----
            float mx0 = -1e30f, mx1 = -1e30f;
#pragma unroll
            for (int j = 0; j < 8; j++) {
                int colb = kb * 64 + j * 8 + 2 * q;
                float v0 = sacc[j][0] * scale; if (colb     > gr0) v0 = -1e30f;
                float v1 = sacc[j][1] * scale; if (colb + 1 > gr0) v1 = -1e30f;
                float v2 = sacc[j][2] * scale; if (colb     > gr1) v2 = -1e30f;
                float v3 = sacc[j][3] * scale; if (colb + 1 > gr1) v3 = -1e30f;
                sacc[j][0] = v0; sacc[j][1] = v1; sacc[j][2] = v2; sacc[j][3] = v3;
                mx0 = fmaxf(mx0, fmaxf(v0, v1));
                mx1 = fmaxf(mx1, fmaxf(v2, v3));
            }
            mx0 = fmaxf(mx0, __shfl_xor_sync(0xffffffffu, mx0, 1));
            mx0 = fmaxf(mx0, __shfl_xor_sync(0xffffffffu, mx0, 2));
            mx1 = fmaxf(mx1, __shfl_xor_sync(0xffffffffu, mx1, 1));
            mx1 = fmaxf(mx1, __shfl_xor_sync(0xffffffffu, mx1, 2));

            float mn0 = fmaxf(m_old0, mx0), mn1 = fmaxf(m_old1, mx1);
            float al0 = fexp(m_old0 - mn0), al1 = fexp(m_old1 - mn1);
            float ps0 = 0.f, ps1 = 0.f;
            float* Pr0 = sm + OFF_P + (size_t)(16 * wid + g) * 68;
            float* Pr1 = Pr0 + 8 * 68;
#pragma unroll
            for (int j = 0; j < 8; j++) {
                float p0 = fexp(sacc[j][0] - mn0);
                float p1 = fexp(sacc[j][1] - mn0);
                float p2 = fexp(sacc[j][2] - mn1);
                float p3 = fexp(sacc[j][3] - mn1);
                ps0 += p0 + p1; ps1 += p2 + p3;
                *(float2*)&Pr0[j * 8 + 2 * q] = make_float2(p0, p1);
                *(float2*)&Pr1[j * 8 + 2 * q] = make_float2(p2, p3);
            }
            ps0 += __shfl_xor_sync(0xffffffffu, ps0, 1);
            ps0 += __shfl_xor_sync(0xffffffffu, ps0, 2);
            ps1 += __shfl_xor_sync(0xffffffffu, ps1, 1);
            ps1 += __shfl_xor_sync(0xffffffffu, ps1, 2);
            l0 = l0 * al0 + ps0; l1 = l1 * al1 + ps1;
            m_old0 = mn0; m_old1 = mn1;
#pragma unroll
            for (int jt = 0; jt < 16; jt++) {
                o[jt][0] *= al0; o[jt][1] *= al0;
                o[jt][2] *= al1; o[jt][3] *= al1;
            }
        }

        CP_WAIT(1);
        __syncthreads();   // V_kb ready

        if (active) {
            const float* Vs = sm + OFF_V;
            const float* Pw = sm + OFF_P + (size_t)(16 * wid) * 68;
#pragma unroll 2
            for (int ks = 0; ks < 8; ks++) {
                uint32_t Ah[4], Al[4];
                int cc = ks * 8 + q;
                split32(Pw[g * 68 + cc],           Ah[0], Al[0]);
                split32(Pw[(g + 8) * 68 + cc],     Ah[1], Al[1]);
                split32(Pw[g * 68 + cc + 4],       Ah[2], Al[2]);
                split32(Pw[(g + 8) * 68 + cc + 4], Ah[3], Al[3]);
#pragma unroll
                for (int jt = 0; jt < 16; jt++) {
                    uint32_t Bh[2], Bl[2];
                    split32(Vs[cc * 132 + jt * 8 + g],       Bh[0], Bl[0]);
                    split32(Vs[(cc + 4) * 132 + jt * 8 + g], Bh[1], Bl[1]);
                    mma_tf32(o[jt], Ah, Bh);
                    mma_tf32(o[jt], Al, Bh);
                    mma_tf32(o[jt], Ah, Bl);
                }
            }
        }

        __syncthreads();   // all warps done with V_kb

        // g) issue V_{kb+1}
        if (kb < kmax) {
            int tk = (kb + 1) * 64;
#pragma unroll
            for (int j = 0; j < 8; j++) {
                int f = tid + j * 256;
                int row = f >> 5, c4 = f & 31;
                cp16(smb + (OFF_V + row * 132 + c4 * 4) * 4,
                     &vl[(size_t)(rowbase + tk + row) * 2048 + h * DH + c4 * 4]);
            }
        }
        CP_COMMIT();
    }

    // ---- epilogue ----
    float inv0 = 1.f / l0, inv1 = 1.f / l1;
    size_t ob0 = (size_t)(rowbase + gr0) * CDIM + h * DH;
    size_t ob1 = (size_t)(rowbase + gr1) * CDIM + h * DH;
#pragma unroll
    for (int jt = 0; jt < 16; jt++) {
        *(float2*)&Og[ob0 + jt * 8 + 2 * q] =
            make_float2(o[jt][0] * inv0, o[jt][1] * inv0);
        *(float2*)&Og[ob1 + jt * 8 + 2 * q] =
            make_float2(o[jt][2] * inv1, o[jt][3] * inv1);
    }
}

// ------------------------------- launch ------------------------------------
static void launch_gemm(const float* A, const float* B, float* C,
                        int M, int N, int K)
{
    dim3 grid(N / 128, M / 128);
    gemm_mma<<<grid, 256, GEMM_SMEM>>>(A, B, C, M, N, K);
}

extern "C" void kernel_launch(void* const* d_in, const int* in_sizes, int n_in,
                              void* d_out, int out_size)
{
    (void)in_sizes; (void)n_in; (void)out_size;
    const float* x    = (const float*)d_in[0];
    const float* WkvD = (const float*)d_in[1];
    const float* WqD  = (const float*)d_in[2];
    const float* WkU  = (const float*)d_in[3];
    const float* WvU  = (const float*)d_in[4];
    const float* WqU  = (const float*)d_in[5];
    const float* Wrk  = (const float*)d_in[6];
    const float* Wrq  = (const float*)d_in[7];
    const float* Wo   = (const float*)d_in[8];
    float* out = (float*)d_out;

    float *kvd, *qd, *kc, *qc, *vl, *kr, *qr, *attn;
    cudaGetSymbolAddress((void**)&kvd,  g_kvd);
    cudaGetSymbolAddress((void**)&qd,   g_qd);
    cudaGetSymbolAddress((void**)&kc,   g_kc);
    cudaGetSymbolAddress((void**)&qc,   g_qc);
    cudaGetSymbolAddress((void**)&vl,   g_vl);
    cudaGetSymbolAddress((void**)&kr,   g_kr);
    cudaGetSymbolAddress((void**)&qr,   g_qr);
    cudaGetSymbolAddress((void**)&attn, g_attn);

    cudaFuncSetAttribute(gemm_mma, cudaFuncAttributeMaxDynamicSharedMemorySize,
                         GEMM_SMEM);
    cudaFuncSetAttribute(attn_mma, cudaFuncAttributeMaxDynamicSharedMemorySize,
                         ATTN_SMEM);

    // projections (tensor cores, 3xTF32)
    launch_gemm(x,   WkvD, kvd, ROWS,  LDIM, CDIM);
    launch_gemm(x,   WqD,  qd,  ROWS,  LDIM, CDIM);
    launch_gemm(kvd, WkU,  kc,  ROWS,  1024, LDIM);
    launch_gemm(qd,  WqU,  qc,  ROWS,  1024, LDIM);
    launch_gemm(kvd, WvU,  vl,  ROWS,  CDIM, LDIM);
    launch_gemm(x,   Wrk,  kr,  ROWS,  1024, CDIM);
    launch_gemm(qd,  Wrq,  qr,  ROWS,  1024, LDIM);

    // fused rope on kr and qr
    {
        int n = ROWS * 512;
        rope2_kernel<<<(n + 255) / 256, 256>>>(kr, qr);
    }

    // flash attention (tensor cores), reads projections directly
    {
        dim3 grid(TDIM / 128, HNUM, 2);
        attn_mma<<<grid, 256, ATTN_SMEM>>>(qc, qr, kc, kr, vl, attn);
    }

    // output projection (tensor cores)
    launch_gemm(attn, Wo, out, ROWS, CDIM, CDIM);
}

// round 5
// speedup vs baseline: 2.0944x; 1.1356x over previous
#include <cuda_runtime.h>
#include <cuda_bf16.h>
#include <math.h>
#include <stdint.h>

// ---------------------------------------------------------------------------
// MLA forward. Projections: mma.sync tf32 (3xTF32). Attention: mma.sync bf16
// (bf16x3 emulation, operands pre-split hi/mid in smem).
// B=2, T=2048, C=2048, H=16, DH=128, L=512, hd2=64, rows = B*T = 4096
// ---------------------------------------------------------------------------

#define ROWS 4096
#define TDIM 2048
#define CDIM 2048
#define LDIM 512
#define HNUM 16
#define DH   128
#define HD2  64

// ------------------------- scratch (device globals) ------------------------
__device__ float g_kvd [ROWS * LDIM];
__device__ float g_qd  [ROWS * LDIM];
__device__ float g_kc  [ROWS * 1024];
__device__ float g_qc  [ROWS * 1024];
__device__ float g_vl  [ROWS * CDIM];
__device__ float g_kr  [ROWS * 1024];
__device__ float g_qr  [ROWS * 1024];
__device__ float g_attn[ROWS * CDIM];

// =========================== helpers =======================================
__device__ __forceinline__ uint32_t smem_u32(const void* p) {
    uint32_t a;
    asm("{ .reg .u64 t; cvta.to.shared.u64 t, %1; cvt.u32.u64 %0, t; }"
        : "=r"(a) : "l"(p));
    return a;
}

__device__ __forceinline__ void cp16(uint32_t dst, const void* src) {
    asm volatile("cp.async.cg.shared.global [%0], [%1], 16;"
                 :: "r"(dst), "l"(src));
}
#define CP_COMMIT() asm volatile("cp.async.commit_group;" ::: "memory")
#define CP_WAIT(n)  asm volatile("cp.async.wait_group %0;" :: "n"(n) : "memory")

__device__ __forceinline__ uint32_t tf32_hi(float x) {
    uint32_t u;
    asm("cvt.rna.tf32.f32 %0, %1;" : "=r"(u) : "f"(x));
    return u;
}
__device__ __forceinline__ void split32(float x, uint32_t& hi, uint32_t& lo) {
    hi = tf32_hi(x);
    lo = __float_as_uint(x - __uint_as_float(hi));
}

// D += A * B  (m16n8k8 tf32, row.col)
__device__ __forceinline__ void mma_tf32(float* d, const uint32_t* a,
                                         const uint32_t* b) {
    asm volatile(
        "mma.sync.aligned.m16n8k8.row.col.f32.tf32.tf32.f32 "
        "{%0,%1,%2,%3}, {%4,%5,%6,%7}, {%8,%9}, {%0,%1,%2,%3};"
        : "+f"(d[0]), "+f"(d[1]), "+f"(d[2]), "+f"(d[3])
        : "r"(a[0]), "r"(a[1]), "r"(a[2]), "r"(a[3]), "r"(b[0]), "r"(b[1]));
}

// D += A * B  (m16n8k16 bf16, row.col)
__device__ __forceinline__ void mma_bf16(float* d, const uint32_t* a,
                                         const uint32_t* b) {
    asm volatile(
        "mma.sync.aligned.m16n8k16.row.col.f32.bf16.bf16.f32 "
        "{%0,%1,%2,%3}, {%4,%5,%6,%7}, {%8,%9}, {%0,%1,%2,%3};"
        : "+f"(d[0]), "+f"(d[1]), "+f"(d[2]), "+f"(d[3])
        : "r"(a[0]), "r"(a[1]), "r"(a[2]), "r"(a[3]), "r"(b[0]), "r"(b[1]));
}

// split (x0,x1) -> packed bf16x2 hi word + mid word (low half = x0)
__device__ __forceinline__ void split_pack(float x0, float x1,
                                           uint32_t& wh, uint32_t& wm) {
    __nv_bfloat162 hh = __floats2bfloat162_rn(x0, x1);
    float f0 = __low2float(hh), f1 = __high2float(hh);
    __nv_bfloat162 mm = __floats2bfloat162_rn(x0 - f0, x1 - f1);
    wh = reinterpret_cast<uint32_t&>(hh);
    wm = reinterpret_cast<uint32_t&>(mm);
}

// fast exp on the FMA pipe (x <= 0), rel err ~1.2e-7
__device__ __forceinline__ float fexp(float x) {
    float t  = x * 1.4426950408889634f;
    float kf = rintf(t);
    float y  = (t - kf) * 0.6931471805599453f;
    float r  = fmaf(y, 1.3888888889e-3f, 8.3333333333e-3f);
    r = fmaf(y, r, 4.1666666667e-2f);
    r = fmaf(y, r, 1.6666666667e-1f);
    r = fmaf(y, r, 0.5f);
    r = fmaf(y, r, 1.0f);
    r = fmaf(y, r, 1.0f);
    int ki = (int)fmaxf(kf, -127.0f);
    return r * __int_as_float((ki + 127) << 23);
}

// ====================== mma.sync 3xTF32 GEMM (proven) ======================
#define GPAD     36
#define GST_B    (128 * GPAD * 4)
#define GSTAGE_B (2 * GST_B)
#define GEMM_SMEM (3 * GSTAGE_B)

__global__ __launch_bounds__(256) void gemm_mma(
    const float* __restrict__ A, const float* __restrict__ B,
    float* __restrict__ C, int M, int N, int K)
{
    extern __shared__ __align__(16) float sm[];
    const uint32_t smb = smem_u32(sm);
    const int tid  = threadIdx.x;
    const int wid  = tid >> 5, lane = tid & 31;
    const int wm   = wid >> 2, wn = wid & 3;
    const int r    = lane >> 2, q = lane & 3;
    const int bm   = blockIdx.y * 128, bn = blockIdx.x * 128;

    float c[4][4][4];
#pragma unroll
    for (int i = 0; i < 4; i++)
#pragma unroll
        for (int j = 0; j < 4; j++)
#pragma unroll
            for (int e = 0; e < 4; e++) c[i][j][e] = 0.f;

    const int KT = K / 32;

    auto issue = [&](int s, int k0) {
#pragma unroll
        for (int j = 0; j < 4; j++) {
            int f = tid + j * 256;
            int row = f >> 3, c4 = f & 7;
            uint32_t off = (uint32_t)(s * GSTAGE_B + row * (GPAD * 4) + c4 * 16);
            cp16(smb + off, &A[(size_t)(bm + row) * K + k0 + c4 * 4]);
            cp16(smb + off + GST_B, &B[(size_t)(bn + row) * K + k0 + c4 * 4]);
        }
    };

    issue(0, 0);  CP_COMMIT();
    issue(1, 32); CP_COMMIT();

    for (int it = 0; it < KT; it++) {
        CP_WAIT(1);
        __syncthreads();

        if (it + 2 < KT) issue((it + 2) % 3, (it + 2) * 32);
        CP_COMMIT();

        const float* As = sm + (it % 3) * (GSTAGE_B / 4);
        const float* Bs = As + (GST_B / 4);

#pragma unroll
        for (int ks = 0; ks < 4; ks++) {
            uint32_t Ahi[4][4], Alo[4][4], Bhi[4][2], Blo[4][2];
#pragma unroll
            for (int i = 0; i < 4; i++) {
                int rb = wm * 64 + i * 16 + r;
                int cc = ks * 8 + q;
                split32(As[rb * GPAD + cc],           Ahi[i][0], Alo[i][0]);
                split32(As[(rb + 8) * GPAD + cc],     Ahi[i][1], Alo[i][1]);
                split32(As[rb * GPAD + cc + 4],       Ahi[i][2], Alo[i][2]);
                split32(As[(rb + 8) * GPAD + cc + 4], Ahi[i][3], Alo[i][3]);
            }
#pragma unroll
            for (int j = 0; j < 4; j++) {
                int nb = wn * 32 + j * 8 + r;
                int cc = ks * 8 + q;
                split32(Bs[nb * GPAD + cc],     Bhi[j][0], Blo[j][0]);
                split32(Bs[nb * GPAD + cc + 4], Bhi[j][1], Blo[j][1]);
            }
#pragma unroll
            for (int i = 0; i < 4; i++)
#pragma unroll
                for (int j = 0; j < 4; j++) {
                    mma_tf32(c[i][j], Ahi[i], Bhi[j]);
                    mma_tf32(c[i][j], Alo[i], Bhi[j]);
                    mma_tf32(c[i][j], Ahi[i], Blo[j]);
                }
        }
    }

#pragma unroll
    for (int i = 0; i < 4; i++)
#pragma unroll
        for (int j = 0; j < 4; j++) {
            int row0 = bm + wm * 64 + i * 16 + r;
            int col  = bn + wn * 32 + j * 8 + 2 * q;
            *(float2*)&C[(size_t)row0 * N + col]       = make_float2(c[i][j][0], c[i][j][1]);
            *(float2*)&C[(size_t)(row0 + 8) * N + col] = make_float2(c[i][j][2], c[i][j][3]);
        }
}

// ------------------------------- RoPE (fused kr+qr) ------------------------
__global__ void rope2_kernel(float* __restrict__ xk, float* __restrict__ xq)
{
    int idx = blockIdx.x * blockDim.x + threadIdx.x;
    if (idx >= ROWS * 512) return;
    int pair = idx & 511;
    int row  = idx >> 9;
    int t    = row & (TDIM - 1);

    const float c1 = (float)(-9.210340371976184 / 1024.0);
    float f   = expf((float)(2 * pair) * c1);
    float ang = (float)t * f;

    double ad = (double)ang;
    double rr = ad - floor(ad * 0.15915494309189535) * 6.283185307179586;
    float s = sinf((float)rr);
    float c = cosf((float)rr);

    {
        float* p = xk + (size_t)row * 1024 + 2 * pair;
        float xe = p[0], xo = p[1];
        p[0] = xe * c - xo * s;
        p[1] = xo * c + xe * s;
    }
    {
        float* p = xq + (size_t)row * 1024 + 2 * pair;
        float xe = p[0], xo = p[1];
        p[0] = xe * c - xo * s;
        p[1] = xo * c + xe * s;
    }
}

// ====================== bf16x3 flash attention =============================
// CTA: 128 q-rows x (h, b); 8 warps, each owns 16 q-rows (warp-local softmax).
// K-tile = 64 keys. All operands pre-split (hi+mid bf16, packed bf16x2 words)
// in smem; inner loops are LDS -> mma.m16n8k16.bf16 only.
// smem word offsets (uint32 units):
#define AQH 0            // Q hi  [128][68]
#define AQM 8704         // Q mid
#define AKH 17408        // K hi  [64][68]
#define AKM 21760
#define AVH 26112        // V^T hi [128 d][36]  (keys packed in pairs)
#define AVM 30720
#define APH 35328        // P hi  [128][36]
#define APM 39936
#define ATTN_SMEM (44544 * 4)    // 178176 B

__global__ __launch_bounds__(256) void attn_bf3(
    const float* __restrict__ qc, const float* __restrict__ qr,
    const float* __restrict__ kc, const float* __restrict__ kr,
    const float* __restrict__ vl, float* __restrict__ Og)
{
    extern __shared__ uint32_t smw[];
    const int tid = threadIdx.x, wid = tid >> 5, lane = tid & 31;
    const int g = lane >> 2, q = lane & 3;
    const int qb = blockIdx.x, h = blockIdx.y, b = blockIdx.z;
    const int q0 = qb * 128;
    const int rowbase = b * TDIM;
    const float scale = 0.08838834764831845f;   // 1/sqrt(128)

    uint32_t* QH = smw + AQH;  uint32_t* QM = smw + AQM;
    uint32_t* KH = smw + AKH;  uint32_t* KM = smw + AKM;
    uint32_t* VH = smw + AVH;  uint32_t* VM = smw + AVM;
    uint32_t* PH = smw + APH;  uint32_t* PM = smw + APM;

    // ---- Q prologue: load, split, store (once) ----
    {
        int row = tid >> 1, kh = tid & 1;    // kh: low/high 64 of headdim
        const float* src = kh
            ? &qr[(size_t)(rowbase + q0 + row) * 1024 + h * HD2]
            : &qc[(size_t)(rowbase + q0 + row) * 1024 + h * HD2];
        int wbase = row * 68 + kh * 32;
#pragma unroll
        for (int f = 0; f < 16; f++) {
            float4 v = *(const float4*)&src[f * 4];
            uint32_t h0, m0, h1, m1;
            split_pack(v.x, v.y, h0, m0);
            split_pack(v.z, v.w, h1, m1);
            QH[wbase + f * 2] = h0; QH[wbase + f * 2 + 1] = h1;
            QM[wbase + f * 2] = m0; QM[wbase + f * 2 + 1] = m1;
        }
    }

    // ---- K/V register prefetch + split-store helpers ----
    float4 kreg[8], vreg[8];
    const int krow = tid >> 2, kq = tid & 3;       // K: row, k-quarter
    const int vp = tid & 31, vdg = tid >> 5;       // V: key-pair, d-group

    auto ldK = [&](int tk) {
        const float* src = (kq < 2)
            ? &kc[(size_t)(rowbase + tk + krow) * 1024 + h * HD2 + kq * 32]
            : &kr[(size_t)(rowbase + tk + krow) * 1024 + h * HD2 + (kq - 2) * 32];
#pragma unroll
        for (int f = 0; f < 8; f++) kreg[f] = *(const float4*)&src[f * 4];
    };
    auto stK = [&]() {
        int wbase = krow * 68 + kq * 16;
#pragma unroll
        for (int f = 0; f < 8; f++) {
            uint32_t h0, m0, h1, m1;
            split_pack(kreg[f].x, kreg[f].y, h0, m0);
            split_pack(kreg[f].z, kreg[f].w, h1, m1);
            KH[wbase + f * 2] = h0; KH[wbase + f * 2 + 1] = h1;
            KM[wbase + f * 2] = m0; KM[wbase + f * 2 + 1] = m1;
        }
    };
    auto ldV = [&](int tk) {
        const float* s0 = &vl[(size_t)(rowbase + tk + 2 * vp) * 2048 + h * DH + vdg * 16];
        const float* s1 = s0 + 2048;
#pragma unroll
        for (int f = 0; f < 4; f++) {
            vreg[f]     = *(const float4*)&s0[f * 4];
            vreg[4 + f] = *(const float4*)&s1[f * 4];
        }
    };
    auto stV = [&]() {
#pragma unroll
        for (int f = 0; f < 4; f++) {
            float a[4] = {vreg[f].x, vreg[f].y, vreg[f].z, vreg[f].w};
            float c2[4] = {vreg[4+f].x, vreg[4+f].y, vreg[4+f].z, vreg[4+f].w};
#pragma unroll
            for (int e = 0; e < 4; e++) {
                uint32_t hw, mw;
                split_pack(a[e], c2[e], hw, mw);   // low=key 2p, high=key 2p+1
                int d = vdg * 16 + f * 4 + e;
                VH[d * 36 + vp] = hw;
                VM[d * 36 + vp] = mw;
            }
        }
    };

    float o[16][4];
#pragma unroll
    for (int jt = 0; jt < 16; jt++)
#pragma unroll
        for (int e = 0; e < 4; e++) o[jt][e] = 0.f;
    float m_old0 = -1e30f, m_old1 = -1e30f, l0 = 0.f, l1 = 0.f;

    const int kmax = 2 * qb + 1;
    const int gr0 = q0 + 16 * wid + g, gr1 = gr0 + 8;
    const int qwr = 16 * wid;          // warp's first q-row in tile

    ldK(0); ldV(0);

    for (int kb = 0; kb <= kmax; kb++) {
        __syncthreads();          // bf16 tile buffers free (prev iter done)
        stK(); stV();
        if (kb < kmax) { ldK((kb + 1) * 64); ldV((kb + 1) * 64); }
        __syncthreads();          // tiles ready

        const bool active = (kb * 64 <= q0 + qwr + 15);
        if (active) {
            // ---- S = Q K^T (bf16x3) ----
            float sacc[8][4];
#pragma unroll
            for (int j = 0; j < 8; j++)
#pragma unroll
                for (int e = 0; e < 4; e++) sacc[j][e] = 0.f;

#pragma unroll
            for (int c = 0; c < 8; c++) {
                uint32_t Ah[4], Am[4];
                int aw = (qwr + g) * 68 + c * 8 + q;
                Ah[0] = QH[aw];            Am[0] = QM[aw];
                Ah[1] = QH[aw + 8 * 68];   Am[1] = QM[aw + 8 * 68];
                Ah[2] = QH[aw + 4];        Am[2] = QM[aw + 4];
                Ah[3] = QH[aw + 8 * 68 + 4]; Am[3] = QM[aw + 8 * 68 + 4];
#pragma unroll
                for (int j = 0; j < 8; j++) {
                    uint32_t Bh[2], Bm[2];
                    int bw = (j * 8 + g) * 68 + c * 8 + q;
                    Bh[0] = KH[bw];     Bh[1] = KH[bw + 4];
                    Bm[0] = KM[bw];     Bm[1] = KM[bw + 4];
                    mma_bf16(sacc[j], Ah, Bh);
                    mma_bf16(sacc[j], Ah, Bm);
                    mma_bf16(sacc[j], Am, Bh);
                }
            }

            // ---- scale + causal mask + online softmax ----
            float mx0 = -1e30f, mx1 = -1e30f;
#pragma unroll
            for (int j = 0; j < 8; j++) {
                int colb = kb * 64 + j * 8 + 2 * q;
                float v0 = sacc[j][0] * scale; if (colb     > gr0) v0 = -1e30f;
                float v1 = sacc[j][1] * scale; if (colb + 1 > gr0) v1 = -1e30f;
                float v2 = sacc[j][2] * scale; if (colb     > gr1) v2 = -1e30f;
                float v3 = sacc[j][3] * scale; if (colb + 1 > gr1) v3 = -1e30f;
                sacc[j][0] = v0; sacc[j][1] = v1; sacc[j][2] = v2; sacc[j][3] = v3;
                mx0 = fmaxf(mx0, fmaxf(v0, v1));
                mx1 = fmaxf(mx1, fmaxf(v2, v3));
            }
            mx0 = fmaxf(mx0, __shfl_xor_sync(0xffffffffu, mx0, 1));
            mx0 = fmaxf(mx0, __shfl_xor_sync(0xffffffffu, mx0, 2));
            mx1 = fmaxf(mx1, __shfl_xor_sync(0xffffffffu, mx1, 1));
            mx1 = fmaxf(mx1, __shfl_xor_sync(0xffffffffu, mx1, 2));

            float mn0 = fmaxf(m_old0, mx0), mn1 = fmaxf(m_old1, mx1);
            float al0 = fexp(m_old0 - mn0), al1 = fexp(m_old1 - mn1);
            float ps0 = 0.f, ps1 = 0.f;
#pragma unroll
            for (int j = 0; j < 8; j++) {
                float p0 = fexp(sacc[j][0] - mn0);
                float p1 = fexp(sacc[j][1] - mn0);
                float p2 = fexp(sacc[j][2] - mn1);
                float p3 = fexp(sacc[j][3] - mn1);
                ps0 += p0 + p1; ps1 += p2 + p3;
                uint32_t hw, mw;
                split_pack(p0, p1, hw, mw);
                PH[(qwr + g) * 36 + j * 4 + q] = hw;
                PM[(qwr + g) * 36 + j * 4 + q] = mw;
                split_pack(p2, p3, hw, mw);
                PH[(qwr + g + 8) * 36 + j * 4 + q] = hw;
                PM[(qwr + g + 8) * 36 + j * 4 + q] = mw;
            }
            ps0 += __shfl_xor_sync(0xffffffffu, ps0, 1);
            ps0 += __shfl_xor_sync(0xffffffffu, ps0, 2);
            ps1 += __shfl_xor_sync(0xffffffffu, ps1, 1);
            ps1 += __shfl_xor_sync(0xffffffffu, ps1, 2);
            l0 = l0 * al0 + ps0; l1 = l1 * al1 + ps1;
            m_old0 = mn0; m_old1 = mn1;
#pragma unroll
            for (int jt = 0; jt < 16; jt++) {
                o[jt][0] *= al0; o[jt][1] *= al0;
                o[jt][2] *= al1; o[jt][3] *= al1;
            }

            __syncwarp();   // P rows produced+consumed within this warp

            // ---- O += P V (bf16x3) ----
#pragma unroll
            for (int c = 0; c < 4; c++) {
                uint32_t Ah[4], Am[4];
                int aw = (qwr + g) * 36 + c * 8 + q;
                Ah[0] = PH[aw];            Am[0] = PM[aw];
                Ah[1] = PH[aw + 8 * 36];   Am[1] = PM[aw + 8 * 36];
                Ah[2] = PH[aw + 4];        Am[2] = PM[aw + 4];
                Ah[3] = PH[aw + 8 * 36 + 4]; Am[3] = PM[aw + 8 * 36 + 4];
#pragma unroll
                for (int jt = 0; jt < 16; jt++) {
                    uint32_t Bh[2], Bm[2];
                    int bw = (jt * 8 + g) * 36 + c * 8 + q;
                    Bh[0] = VH[bw];     Bh[1] = VH[bw + 4];
                    Bm[0] = VM[bw];     Bm[1] = VM[bw + 4];
                    mma_bf16(o[jt], Ah, Bh);
                    mma_bf16(o[jt], Ah, Bm);
                    mma_bf16(o[jt], Am, Bh);
                }
            }
        }
    }

    // ---- epilogue ----
    float inv0 = 1.f / l0, inv1 = 1.f / l1;
    size_t ob0 = (size_t)(rowbase + gr0) * CDIM + h * DH;
    size_t ob1 = (size_t)(rowbase + gr1) * CDIM + h * DH;
#pragma unroll
    for (int jt = 0; jt < 16; jt++) {
        *(float2*)&Og[ob0 + jt * 8 + 2 * q] =
            make_float2(o[jt][0] * inv0, o[jt][1] * inv0);
        *(float2*)&Og[ob1 + jt * 8 + 2 * q] =
            make_float2(o[jt][2] * inv1, o[jt][3] * inv1);
    }
}

// ------------------------------- launch ------------------------------------
static void launch_gemm(const float* A, const float* B, float* C,
                        int M, int N, int K)
{
    dim3 grid(N / 128, M / 128);
    gemm_mma<<<grid, 256, GEMM_SMEM>>>(A, B, C, M, N, K);
}

extern "C" void kernel_launch(void* const* d_in, const int* in_sizes, int n_in,
                              void* d_out, int out_size)
{
    (void)in_sizes; (void)n_in; (void)out_size;
    const float* x    = (const float*)d_in[0];
    const float* WkvD = (const float*)d_in[1];
    const float* WqD  = (const float*)d_in[2];
    const float* WkU  = (const float*)d_in[3];
    const float* WvU  = (const float*)d_in[4];
    const float* WqU  = (const float*)d_in[5];
    const float* Wrk  = (const float*)d_in[6];
    const float* Wrq  = (const float*)d_in[7];
    const float* Wo   = (const float*)d_in[8];
    float* out = (float*)d_out;

    float *kvd, *qd, *kc, *qc, *vl, *kr, *qr, *attn;
    cudaGetSymbolAddress((void**)&kvd,  g_kvd);
    cudaGetSymbolAddress((void**)&qd,   g_qd);
    cudaGetSymbolAddress((void**)&kc,   g_kc);
    cudaGetSymbolAddress((void**)&qc,   g_qc);
    cudaGetSymbolAddress((void**)&vl,   g_vl);
    cudaGetSymbolAddress((void**)&kr,   g_kr);
    cudaGetSymbolAddress((void**)&qr,   g_qr);
    cudaGetSymbolAddress((void**)&attn, g_attn);

    cudaFuncSetAttribute(gemm_mma, cudaFuncAttributeMaxDynamicSharedMemorySize,
                         GEMM_SMEM);
    cudaFuncSetAttribute(attn_bf3, cudaFuncAttributeMaxDynamicSharedMemorySize,
                         ATTN_SMEM);

    // projections (tensor cores, 3xTF32)
    launch_gemm(x,   WkvD, kvd, ROWS,  LDIM, CDIM);
    launch_gemm(x,   WqD,  qd,  ROWS,  LDIM, CDIM);
    launch_gemm(kvd, WkU,  kc,  ROWS,  1024, LDIM);
    launch_gemm(qd,  WqU,  qc,  ROWS,  1024, LDIM);
    launch_gemm(kvd, WvU,  vl,  ROWS,  CDIM, LDIM);
    launch_gemm(x,   Wrk,  kr,  ROWS,  1024, CDIM);
    launch_gemm(qd,  Wrq,  qr,  ROWS,  1024, LDIM);

    // fused rope on kr and qr
    {
        int n = ROWS * 512;
        rope2_kernel<<<(n + 255) / 256, 256>>>(kr, qr);
    }

    // flash attention (bf16x3 tensor cores)
    {
        dim3 grid(TDIM / 128, HNUM, 2);
        attn_bf3<<<grid, 256, ATTN_SMEM>>>(qc, qr, kc, kr, vl, attn);
    }

    // output projection (tensor cores)
    launch_gemm(attn, Wo, out, ROWS, CDIM, CDIM);
}

// round 6
// speedup vs baseline: 2.2872x; 1.0921x over previous
#include <cuda_runtime.h>
#include <cuda_bf16.h>
#include <math.h>
#include <stdint.h>

// ---------------------------------------------------------------------------
// MLA forward. Projections: segmented mma.sync tf32 (3xTF32) batch GEMMs.
// Attention: mma.sync bf16 (bf16x3), operands pre-split to global bf16 hi/mid
// arrays (rope fused into the K/Q split), pure cp.async pipeline in-kernel.
// B=2, T=2048, C=2048, H=16, DH=128, L=512, rows = 4096
// ---------------------------------------------------------------------------

#define ROWS 4096
#define TDIM 2048
#define CDIM 2048
#define HNUM 16
#define DH   128
#define HD2  64

// ------------------------- scratch (device globals) ------------------------
__device__ float g_kvd [ROWS * 512];
__device__ float g_qd  [ROWS * 512];
__device__ float g_kc  [ROWS * 1024];
__device__ float g_qc  [ROWS * 1024];
__device__ float g_vl  [ROWS * 2048];
__device__ float g_kr  [ROWS * 1024];
__device__ float g_qr  [ROWS * 1024];
__device__ float g_attn[ROWS * 2048];
// pre-split bf16x2 words: Q/K [row][1024 w] (per head 64 w: 32 "c" + 32 "r")
__device__ uint32_t g_QH[ROWS * 1024];
__device__ uint32_t g_QM[ROWS * 1024];
__device__ uint32_t g_KH[ROWS * 1024];
__device__ uint32_t g_KM[ROWS * 1024];
// V transposed: [b][h][d 128][key-pair 1024] words
__device__ uint32_t g_VTH[2 * HNUM * 128 * 1024];
__device__ uint32_t g_VTM[2 * HNUM * 128 * 1024];

// =========================== helpers =======================================
__device__ __forceinline__ uint32_t smem_u32(const void* p) {
    uint32_t a;
    asm("{ .reg .u64 t; cvta.to.shared.u64 t, %1; cvt.u32.u64 %0, t; }"
        : "=r"(a) : "l"(p));
    return a;
}
__device__ __forceinline__ void cp16(uint32_t dst, const void* src) {
    asm volatile("cp.async.cg.shared.global [%0], [%1], 16;"
                 :: "r"(dst), "l"(src));
}
#define CP_COMMIT() asm volatile("cp.async.commit_group;" ::: "memory")
#define CP_WAIT(n)  asm volatile("cp.async.wait_group %0;" :: "n"(n) : "memory")

__device__ __forceinline__ uint32_t tf32_hi(float x) {
    uint32_t u;
    asm("cvt.rna.tf32.f32 %0, %1;" : "=r"(u) : "f"(x));
    return u;
}
__device__ __forceinline__ void split32(float x, uint32_t& hi, uint32_t& lo) {
    hi = tf32_hi(x);
    lo = __float_as_uint(x - __uint_as_float(hi));
}
__device__ __forceinline__ void mma_tf32(float* d, const uint32_t* a,
                                         const uint32_t* b) {
    asm volatile(
        "mma.sync.aligned.m16n8k8.row.col.f32.tf32.tf32.f32 "
        "{%0,%1,%2,%3}, {%4,%5,%6,%7}, {%8,%9}, {%0,%1,%2,%3};"
        : "+f"(d[0]), "+f"(d[1]), "+f"(d[2]), "+f"(d[3])
        : "r"(a[0]), "r"(a[1]), "r"(a[2]), "r"(a[3]), "r"(b[0]), "r"(b[1]));
}
__device__ __forceinline__ void mma_bf16(float* d, const uint32_t* a,
                                         const uint32_t* b) {
    asm volatile(
        "mma.sync.aligned.m16n8k16.row.col.f32.bf16.bf16.f32 "
        "{%0,%1,%2,%3}, {%4,%5,%6,%7}, {%8,%9}, {%0,%1,%2,%3};"
        : "+f"(d[0]), "+f"(d[1]), "+f"(d[2]), "+f"(d[3])
        : "r"(a[0]), "r"(a[1]), "r"(a[2]), "r"(a[3]), "r"(b[0]), "r"(b[1]));
}
__device__ __forceinline__ void split_pack(float x0, float x1,
                                           uint32_t& wh, uint32_t& wm) {
    __nv_bfloat162 hh = __floats2bfloat162_rn(x0, x1);
    float f0 = __low2float(hh), f1 = __high2float(hh);
    __nv_bfloat162 mm = __floats2bfloat162_rn(x0 - f0, x1 - f1);
    wh = reinterpret_cast<uint32_t&>(hh);
    wm = reinterpret_cast<uint32_t&>(mm);
}
// fast exp on the FMA pipe (x <= 0)
__device__ __forceinline__ float fexp(float x) {
    float t  = x * 1.4426950408889634f;
    float kf = rintf(t);
    float y  = (t - kf) * 0.6931471805599453f;
    float r  = fmaf(y, 1.3888888889e-3f, 8.3333333333e-3f);
    r = fmaf(y, r, 4.1666666667e-2f);
    r = fmaf(y, r, 1.6666666667e-1f);
    r = fmaf(y, r, 0.5f);
    r = fmaf(y, r, 1.0f);
    r = fmaf(y, r, 1.0f);
    int ki = (int)fmaxf(kf, -127.0f);
    return r * __int_as_float((ki + 127) << 23);
}

// ====================== segmented 3xTF32 batch GEMM ========================
// Up to 3 segments per launch; all share M=4096 and K. C[M,segN] = A*B^T.
struct GemmBatch {
    const float *A0, *B0; float *C0; int ld0, end0;
    const float *A1, *B1; float *C1; int ld1, end1;
    const float *A2, *B2; float *C2; int ld2, end2;
};

#define GPAD     36
#define GST_B    (128 * GPAD * 4)
#define GSTAGE_B (2 * GST_B)
#define GEMM_SMEM (3 * GSTAGE_B)

__global__ __launch_bounds__(256) void gemm_mma(GemmBatch gb, int K)
{
    extern __shared__ __align__(16) float sm[];
    const uint32_t smb = smem_u32(sm);
    const int tid  = threadIdx.x;
    const int wid  = tid >> 5, lane = tid & 31;
    const int wm   = wid >> 2, wn = wid & 3;
    const int r    = lane >> 2, q = lane & 3;
    const int bm   = blockIdx.y * 128;

    const float *A, *B; float* C; int ldC, bn;
    {
        int bx = blockIdx.x;
        if (bx < gb.end0)      { A = gb.A0; B = gb.B0; C = gb.C0; ldC = gb.ld0; bn = bx * 128; }
        else if (bx < gb.end1) { A = gb.A1; B = gb.B1; C = gb.C1; ldC = gb.ld1; bn = (bx - gb.end0) * 128; }
        else                   { A = gb.A2; B = gb.B2; C = gb.C2; ldC = gb.ld2; bn = (bx - gb.end1) * 128; }
    }

    float c[4][4][4];
#pragma unroll
    for (int i = 0; i < 4; i++)
#pragma unroll
        for (int j = 0; j < 4; j++)
#pragma unroll
            for (int e = 0; e < 4; e++) c[i][j][e] = 0.f;

    const int KT = K / 32;

    auto issue = [&](int s, int k0) {
#pragma unroll
        for (int j = 0; j < 4; j++) {
            int f = tid + j * 256;
            int row = f >> 3, c4 = f & 7;
            uint32_t off = (uint32_t)(s * GSTAGE_B + row * (GPAD * 4) + c4 * 16);
            cp16(smb + off, &A[(size_t)(bm + row) * K + k0 + c4 * 4]);
            cp16(smb + off + GST_B, &B[(size_t)(bn + row) * K + k0 + c4 * 4]);
        }
    };

    issue(0, 0);  CP_COMMIT();
    issue(1, 32); CP_COMMIT();

    for (int it = 0; it < KT; it++) {
        CP_WAIT(1);
        __syncthreads();

        if (it + 2 < KT) issue((it + 2) % 3, (it + 2) * 32);
        CP_COMMIT();

        const float* As = sm + (it % 3) * (GSTAGE_B / 4);
        const float* Bs = As + (GST_B / 4);

#pragma unroll
        for (int ks = 0; ks < 4; ks++) {
            uint32_t Ahi[4][4], Alo[4][4], Bhi[4][2], Blo[4][2];
#pragma unroll
            for (int i = 0; i < 4; i++) {
                int rb = wm * 64 + i * 16 + r;
                int cc = ks * 8 + q;
                split32(As[rb * GPAD + cc],           Ahi[i][0], Alo[i][0]);
                split32(As[(rb + 8) * GPAD + cc],     Ahi[i][1], Alo[i][1]);
                split32(As[rb * GPAD + cc + 4],       Ahi[i][2], Alo[i][2]);
                split32(As[(rb + 8) * GPAD + cc + 4], Ahi[i][3], Alo[i][3]);
            }
#pragma unroll
            for (int j = 0; j < 4; j++) {
                int nb = wn * 32 + j * 8 + r;
                int cc = ks * 8 + q;
                split32(Bs[nb * GPAD + cc],     Bhi[j][0], Blo[j][0]);
                split32(Bs[nb * GPAD + cc + 4], Bhi[j][1], Blo[j][1]);
            }
#pragma unroll
            for (int i = 0; i < 4; i++)
#pragma unroll
                for (int j = 0; j < 4; j++) {
                    mma_tf32(c[i][j], Ahi[i], Bhi[j]);
                    mma_tf32(c[i][j], Alo[i], Bhi[j]);
                    mma_tf32(c[i][j], Ahi[i], Blo[j]);
                }
        }
    }

#pragma unroll
    for (int i = 0; i < 4; i++)
#pragma unroll
        for (int j = 0; j < 4; j++) {
            int row0 = bm + wm * 64 + i * 16 + r;
            int col  = bn + wn * 32 + j * 8 + 2 * q;
            *(float2*)&C[(size_t)row0 * ldC + col]       = make_float2(c[i][j][0], c[i][j][1]);
            *(float2*)&C[(size_t)(row0 + 8) * ldC + col] = make_float2(c[i][j][2], c[i][j][3]);
        }
}

// ===================== split kernels (bf16 hi/mid) =========================
// V: transpose to [b][h][d][pair], split. Block = 64 rows x 128 d per (h,b).
__global__ __launch_bounds__(256) void split_v(
    const float* __restrict__ vl, uint32_t* __restrict__ VTH,
    uint32_t* __restrict__ VTM)
{
    __shared__ float smT[128 * 66];
    const int pt = blockIdx.x, h = blockIdx.y, b = blockIdx.z;
    const int t0 = pt * 64, tid = threadIdx.x;
    for (int i = tid; i < 64 * 128; i += 256) {
        int row = i >> 7, col = i & 127;
        smT[col * 66 + row] =
            vl[(size_t)(b * TDIM + t0 + row) * 2048 + h * DH + col];
    }
    __syncthreads();
    const int lane = tid & 31, w = tid >> 5;
#pragma unroll
    for (int pass = 0; pass < 16; pass++) {
        int d = pass * 8 + w;
        float2 v = *(float2*)&smT[d * 66 + 2 * lane];
        uint32_t hw, mw; split_pack(v.x, v.y, hw, mw);
        size_t o = ((size_t)(b * HNUM + h) * 128 + d) * 1024 + pt * 32 + lane;
        VTH[o] = hw; VTM[o] = mw;
    }
}

// Q/K: split + fused interleaved rope on the r-half. blockIdx.y: 0=K, 1=Q.
__global__ __launch_bounds__(256) void split_qk(
    const float* __restrict__ qc, const float* __restrict__ qr,
    const float* __restrict__ kc, const float* __restrict__ kr,
    uint32_t* __restrict__ QH, uint32_t* __restrict__ QM,
    uint32_t* __restrict__ KH, uint32_t* __restrict__ KM)
{
    const int row = blockIdx.x;
    const bool isQ = (blockIdx.y == 1);
    const float* cb = isQ ? qc : kc;
    const float* rb = isQ ? qr : kr;
    uint32_t* OH = isQ ? QH : KH;
    uint32_t* OM = isQ ? QM : KM;
    const int t = row & (TDIM - 1);
#pragma unroll
    for (int j = 0; j < 4; j++) {
        int u = threadIdx.x + j * 256;
        int h = u >> 6, tt = u & 63;
        float2 v;
        if (tt < 32) {
            v = *(const float2*)&cb[(size_t)row * 1024 + h * HD2 + 2 * tt];
        } else {
            int tr = tt - 32;
            v = *(const float2*)&rb[(size_t)row * 1024 + h * HD2 + 2 * tr];
            int pr = h * 32 + tr;
            const float c1 = (float)(-9.210340371976184 / 1024.0);
            float fr  = expf((float)(2 * pr) * c1);
            float ang = (float)t * fr;
            double ad = (double)ang;
            double rr = ad - floor(ad * 0.15915494309189535) * 6.283185307179586;
            float s = sinf((float)rr), c = cosf((float)rr);
            float xe = v.x, xo = v.y;
            v.x = xe * c - xo * s;
            v.y = xo * c + xe * s;
        }
        uint32_t hw, mw; split_pack(v.x, v.y, hw, mw);
        OH[(size_t)row * 1024 + u] = hw;
        OM[(size_t)row * 1024 + u] = mw;
    }
}

// ====================== bf16x3 flash attention =============================
// CTA: 128 q-rows x (h, b); 8 warps x 16 q-rows. K double-buffered,
// V single-buffered, all tiles arrive pre-split via cp.async.
#define AQH 0                 // [128][68]
#define AQM 8704
#define AKH 17408             // 2 slots x [64][68] (slot stride 4352)
#define AKM 26112
#define AVH 34816             // [128][36]
#define AVM 39424
#define APH 44032             // [128][36]
#define APM 48640
#define ATTN_SMEM (53248 * 4) // 212992 B

__global__ __launch_bounds__(256) void attn_bf3(
    const uint32_t* __restrict__ QHg, const uint32_t* __restrict__ QMg,
    const uint32_t* __restrict__ KHg, const uint32_t* __restrict__ KMg,
    const uint32_t* __restrict__ VTHg, const uint32_t* __restrict__ VTMg,
    float* __restrict__ Og)
{
    extern __shared__ uint32_t smw[];
    const uint32_t smb = smem_u32(smw);
    const int tid = threadIdx.x, wid = tid >> 5, lane = tid & 31;
    const int g = lane >> 2, q = lane & 3;
    const int qb = blockIdx.x, h = blockIdx.y, b = blockIdx.z;
    const int q0 = qb * 128, rowbase = b * TDIM;
    const float scale = 0.08838834764831845f;

    uint32_t* QH = smw + AQH;  uint32_t* QM = smw + AQM;
    uint32_t* VH = smw + AVH;  uint32_t* VM = smw + AVM;
    uint32_t* PH = smw + APH;  uint32_t* PM = smw + APM;

    auto cpK = [&](int tk, int slot) {
#pragma unroll
        for (int j = 0; j < 8; j++) {
            int f = tid + j * 256;                   // 0..2047
            int row = (f >> 4) & 63, c4 = f & 15;
            const uint32_t* gsrc = (f < 1024) ? KHg : KMg;
            uint32_t dst = smb + (((f < 1024) ? AKH : AKM) + slot * 4352
                                  + row * 68 + c4 * 4) * 4;
            cp16(dst, gsrc + (size_t)(rowbase + tk + row) * 1024 + h * 64 + c4 * 4);
        }
    };
    auto cpV = [&](int tk) {
#pragma unroll
        for (int j = 0; j < 8; j++) {
            int f = tid + j * 256;
            int d = (f >> 3) & 127, c4 = f & 7;
            const uint32_t* gsrc = (f < 1024) ? VTHg : VTMg;
            uint32_t dst = smb + (((f < 1024) ? AVH : AVM) + d * 36 + c4 * 4) * 4;
            cp16(dst, gsrc + ((size_t)(b * HNUM + h) * 128 + d) * 1024
                        + (tk >> 1) + c4 * 4);
        }
    };

    // prologue: Q + K0 -> G1, V0 -> G2
#pragma unroll
    for (int j = 0; j < 16; j++) {
        int f = tid + j * 256;                       // 0..4095
        int ff = f & 2047;
        int row = (ff >> 4), c4 = ff & 15;
        const uint32_t* gsrc = (f < 2048) ? QHg : QMg;
        uint32_t dst = smb + (((f < 2048) ? AQH : AQM) + row * 68 + c4 * 4) * 4;
        cp16(dst, gsrc + (size_t)(rowbase + q0 + row) * 1024 + h * 64 + c4 * 4);
    }
    cpK(0, 0);
    CP_COMMIT();
    cpV(0);
    CP_COMMIT();

    float o[16][4];
#pragma unroll
    for (int jt = 0; jt < 16; jt++)
#pragma unroll
        for (int e = 0; e < 4; e++) o[jt][e] = 0.f;
    float m_old0 = -1e30f, m_old1 = -1e30f, l0 = 0.f, l1 = 0.f;

    const int kmax = 2 * qb + 1;
    const int gr0 = q0 + 16 * wid + g, gr1 = gr0 + 8;
    const int qwr = 16 * wid;

    for (int kb = 0; kb <= kmax; kb++) {
        if (kb < kmax) cpK((kb + 1) * 64, (kb + 1) & 1);
        CP_COMMIT();
        CP_WAIT(2);
        __syncthreads();      // Q + K_kb ready

        const bool active = (kb * 64 <= q0 + qwr + 15);
        if (active) {
            const uint32_t* KHs = smw + AKH + (kb & 1) * 4352;
            const uint32_t* KMs = smw + AKM + (kb & 1) * 4352;

            float sacc[8][4];
#pragma unroll
            for (int j = 0; j < 8; j++)
#pragma unroll
                for (int e = 0; e < 4; e++) sacc[j][e] = 0.f;

#pragma unroll
            for (int c = 0; c < 8; c++) {
                uint32_t Ah[4], Am[4];
                int aw = (qwr + g) * 68 + c * 8 + q;
                Ah[0] = QH[aw];              Am[0] = QM[aw];
                Ah[1] = QH[aw + 8 * 68];     Am[1] = QM[aw + 8 * 68];
                Ah[2] = QH[aw + 4];          Am[2] = QM[aw + 4];
                Ah[3] = QH[aw + 8 * 68 + 4]; Am[3] = QM[aw + 8 * 68 + 4];
#pragma unroll
                for (int j = 0; j < 8; j++) {
                    uint32_t Bh[2], Bm[2];
                    int bw = (j * 8 + g) * 68 + c * 8 + q;
                    Bh[0] = KHs[bw]; Bh[1] = KHs[bw + 4];
                    Bm[0] = KMs[bw]; Bm[1] = KMs[bw + 4];
                    mma_bf16(sacc[j], Ah, Bh);
                    mma_bf16(sacc[j], Ah, Bm);
                    mma_bf16(sacc[j], Am, Bh);
                }
            }

            float mx0 = -1e30f, mx1 = -1e30f;
#pragma unroll
            for (int j = 0; j < 8; j++) {
                int colb = kb * 64 + j * 8 + 2 * q;
                float v0 = sacc[j][0] * scale; if (colb     > gr0) v0 = -1e30f;
                float v1 = sacc[j][1] * scale; if (colb + 1 > gr0) v1 = -1e30f;
                float v2 = sacc[j][2] * scale; if (colb     > gr1) v2 = -1e30f;
                float v3 = sacc[j][3] * scale; if (colb + 1 > gr1) v3 = -1e30f;
                sacc[j][0] = v0; sacc[j][1] = v1; sacc[j][2] = v2; sacc[j][3] = v3;
                mx0 = fmaxf(mx0, fmaxf(v0, v1));
                mx1 = fmaxf(mx1, fmaxf(v2, v3));
            }
            mx0 = fmaxf(mx0, __shfl_xor_sync(0xffffffffu, mx0, 1));
            mx0 = fmaxf(mx0, __shfl_xor_sync(0xffffffffu, mx0, 2));
            mx1 = fmaxf(mx1, __shfl_xor_sync(0xffffffffu, mx1, 1));
            mx1 = fmaxf(mx1, __shfl_xor_sync(0xffffffffu, mx1, 2));

            float mn0 = fmaxf(m_old0, mx0), mn1 = fmaxf(m_old1, mx1);
            float al0 = fexp(m_old0 - mn0), al1 = fexp(m_old1 - mn1);
            float ps0 = 0.f, ps1 = 0.f;
#pragma unroll
            for (int j = 0; j < 8; j++) {
                float p0 = fexp(sacc[j][0] - mn0);
                float p1 = fexp(sacc[j][1] - mn0);
                float p2 = fexp(sacc[j][2] - mn1);
                float p3 = fexp(sacc[j][3] - mn1);
                ps0 += p0 + p1; ps1 += p2 + p3;
                uint32_t hw, mw;
                split_pack(p0, p1, hw, mw);
                PH[(qwr + g) * 36 + j * 4 + q] = hw;
                PM[(qwr + g) * 36 + j * 4 + q] = mw;
                split_pack(p2, p3, hw, mw);
                PH[(qwr + g + 8) * 36 + j * 4 + q] = hw;
                PM[(qwr + g + 8) * 36 + j * 4 + q] = mw;
            }
            ps0 += __shfl_xor_sync(0xffffffffu, ps0, 1);
            ps0 += __shfl_xor_sync(0xffffffffu, ps0, 2);
            ps1 += __shfl_xor_sync(0xffffffffu, ps1, 1);
            ps1 += __shfl_xor_sync(0xffffffffu, ps1, 2);
            l0 = l0 * al0 + ps0; l1 = l1 * al1 + ps1;
            m_old0 = mn0; m_old1 = mn1;
#pragma unroll
            for (int jt = 0; jt < 16; jt++) {
                o[jt][0] *= al0; o[jt][1] *= al0;
                o[jt][2] *= al1; o[jt][3] *= al1;
            }
        }

        CP_WAIT(1);
        __syncthreads();      // V_kb ready

        if (active) {
            __syncwarp();     // P visible within warp
#pragma unroll
            for (int c = 0; c < 4; c++) {
                uint32_t Ah[4], Am[4];
                int aw = (qwr + g) * 36 + c * 8 + q;
                Ah[0] = PH[aw];              Am[0] = PM[aw];
                Ah[1] = PH[aw + 8 * 36];     Am[1] = PM[aw + 8 * 36];
                Ah[2] = PH[aw + 4];          Am[2] = PM[aw + 4];
                Ah[3] = PH[aw + 8 * 36 + 4]; Am[3] = PM[aw + 8 * 36 + 4];
#pragma unroll
                for (int jt = 0; jt < 16; jt++) {
                    uint32_t Bh[2], Bm[2];
                    int bw = (jt * 8 + g) * 36 + c * 8 + q;
                    Bh[0] = VH[bw]; Bh[1] = VH[bw + 4];
                    Bm[0] = VM[bw]; Bm[1] = VM[bw + 4];
                    mma_bf16(o[jt], Ah, Bh);
                    mma_bf16(o[jt], Ah, Bm);
                    mma_bf16(o[jt], Am, Bh);
                }
            }
        }

        __syncthreads();      // all warps done with V_kb
        if (kb < kmax) cpV((kb + 1) * 64);
        CP_COMMIT();
    }

    float inv0 = 1.f / l0, inv1 = 1.f / l1;
    size_t ob0 = (size_t)(rowbase + gr0) * CDIM + h * DH;
    size_t ob1 = (size_t)(rowbase + gr1) * CDIM + h * DH;
#pragma unroll
    for (int jt = 0; jt < 16; jt++) {
        *(float2*)&Og[ob0 + jt * 8 + 2 * q] =
            make_float2(o[jt][0] * inv0, o[jt][1] * inv0);
        *(float2*)&Og[ob1 + jt * 8 + 2 * q] =
            make_float2(o[jt][2] * inv1, o[jt][3] * inv1);
    }
}

// ------------------------------- launch ------------------------------------
extern "C" void kernel_launch(void* const* d_in, const int* in_sizes, int n_in,
                              void* d_out, int out_size)
{
    (void)in_sizes; (void)n_in; (void)out_size;
    const float* x    = (const float*)d_in[0];
    const float* WkvD = (const float*)d_in[1];
    const float* WqD  = (const float*)d_in[2];
    const float* WkU  = (const float*)d_in[3];
    const float* WvU  = (const float*)d_in[4];
    const float* WqU  = (const float*)d_in[5];
    const float* Wrk  = (const float*)d_in[6];
    const float* Wrq  = (const float*)d_in[7];
    const float* Wo   = (const float*)d_in[8];
    float* out = (float*)d_out;

    float *kvd, *qd, *kc, *qc, *vl, *kr, *qr, *attn;
    uint32_t *QH, *QM, *KH, *KM, *VTH, *VTM;
    cudaGetSymbolAddress((void**)&kvd,  g_kvd);
    cudaGetSymbolAddress((void**)&qd,   g_qd);
    cudaGetSymbolAddress((void**)&kc,   g_kc);
    cudaGetSymbolAddress((void**)&qc,   g_qc);
    cudaGetSymbolAddress((void**)&vl,   g_vl);
    cudaGetSymbolAddress((void**)&kr,   g_kr);
    cudaGetSymbolAddress((void**)&qr,   g_qr);
    cudaGetSymbolAddress((void**)&attn, g_attn);
    cudaGetSymbolAddress((void**)&QH,  g_QH);
    cudaGetSymbolAddress((void**)&QM,  g_QM);
    cudaGetSymbolAddress((void**)&KH,  g_KH);
    cudaGetSymbolAddress((void**)&KM,  g_KM);
    cudaGetSymbolAddress((void**)&VTH, g_VTH);
    cudaGetSymbolAddress((void**)&VTM, g_VTM);

    cudaFuncSetAttribute(gemm_mma, cudaFuncAttributeMaxDynamicSharedMemorySize,
                         GEMM_SMEM);
    cudaFuncSetAttribute(attn_bf3, cudaFuncAttributeMaxDynamicSharedMemorySize,
                         ATTN_SMEM);

    // L1: x -> {kvd, qd, kr}   (K=2048, 4+4+8 nblk)
    {
        GemmBatch gb = { x, WkvD, kvd, 512, 4,
                         x, WqD,  qd,  512, 8,
                         x, Wrk,  kr, 1024, 16 };
        gemm_mma<<<dim3(16, 32), 256, GEMM_SMEM>>>(gb, 2048);
    }
    // L2: {kvd,qd} -> {kc, qc, vl}   (K=512, 8+8+16 nblk)
    {
        GemmBatch gb = { kvd, WkU, kc, 1024, 8,
                         qd,  WqU, qc, 1024, 16,
                         kvd, WvU, vl, 2048, 32 };
        gemm_mma<<<dim3(32, 32), 256, GEMM_SMEM>>>(gb, 512);
    }
    // L3: qd -> qr   (K=512)
    {
        GemmBatch gb = { qd, Wrq, qr, 1024, 8,
                         qd, Wrq, qr, 1024, 8,
                         qd, Wrq, qr, 1024, 8 };
        gemm_mma<<<dim3(8, 32), 256, GEMM_SMEM>>>(gb, 512);
    }
    // L4: split V (transpose + bf16 hi/mid)
    split_v<<<dim3(TDIM / 64, HNUM, 2), 256>>>(vl, VTH, VTM);
    // L5: split Q/K (+ fused rope on r-halves)
    split_qk<<<dim3(ROWS, 2), 256>>>(qc, qr, kc, kr, QH, QM, KH, KM);
    // L6: attention  (this is the ncu-captured launch: -s 5 -c 1)
    attn_bf3<<<dim3(TDIM / 128, HNUM, 2), 256, ATTN_SMEM>>>(
        QH, QM, KH, KM, VTH, VTM, attn);
    // L7: output projection
    {
        GemmBatch gb = { attn, Wo, out, 2048, 16,
                         attn, Wo, out, 2048, 16,
                         attn, Wo, out, 2048, 16 };
        gemm_mma<<<dim3(16, 32), 256, GEMM_SMEM>>>(gb, 2048);
    }
}